// round 1
// baseline (speedup 1.0000x reference)
#include <cuda_runtime.h>

#define NN   5000
#define NE   8000
#define NDIR (2*NE)
#define NC   32
#define HD   64
#define NF   140
#define OPD  8
#define XND  148   // 140 + 8
#define CFD  24
#define POOLD 192  // 3*64

// ---------------- device scratch (static: no runtime allocation) -------------
__device__ __align__(16) float g_xn[NN*XND];
__device__ __align__(16) float g_aggn[NN*XND];
__device__ __align__(16) float g_pernode[NN*HD];
__device__ __align__(16) float g_t1[NC*HD];
__device__ __align__(16) float g_t0[NC*HD];
__device__ __align__(16) float g_h[(size_t)NN*NC*HD];    // 40.96 MB
__device__ __align__(16) float g_agg[(size_t)NN*NC*HD];  // 40.96 MB
__device__ int   g_deg[NN];
__device__ int   g_off[NN+1];
__device__ int   g_cur[NN];
__device__ int   g_adj[NDIR];
__device__ float g_pool[NC*POOLD];
__device__ int   g_op64, g_ed64;

__device__ __forceinline__ int idx_at(const void* p, int i, int is64) {
    if (is64) return (int)((const long long*)p)[i];
    return ((const int*)p)[i];
}

// ---------------- init / dtype detection ------------------------------------
__global__ void k_init() {
    int i = blockIdx.x * blockDim.x + threadIdx.x;
    if (i < NC*POOLD) g_pool[i] = 0.0f;
    if (i < NN) { g_deg[i] = 0; g_cur[i] = 0; }
    if (i == 0) { g_op64 = 1; g_ed64 = 1; }
}

__global__ void k_detect(const void* opc, const void* ei) {
    int i = blockIdx.x * blockDim.x + threadIdx.x;
    // If buffers are int64 (little-endian, small positive values), every odd
    // 32-bit word is 0. Random int32 data cannot satisfy this.
    if (i < 2500) { if (((const unsigned*)opc)[2*i+1] != 0u) g_op64 = 0; }
    if (i < 8000) { if (((const unsigned*)ei )[2*i+1] != 0u) g_ed64 = 0; }
}

// ---------------- node features + op embedding ------------------------------
__global__ void k_xn(const float* __restrict__ nf, const void* __restrict__ opc,
                     const float* __restrict__ op_emb) {
    int idx = blockIdx.x * blockDim.x + threadIdx.x;
    if (idx >= NN*XND) return;
    int n = idx / XND, d = idx % XND;
    if (d < NF) g_xn[idx] = nf[n*NF + d];
    else {
        int op = idx_at(opc, n, g_op64);
        g_xn[idx] = op_emb[op*OPD + (d - NF)];
    }
}

// ---------------- CSR build --------------------------------------------------
__global__ void k_deg(const void* __restrict__ ei) {
    int t = blockIdx.x * blockDim.x + threadIdx.x;
    if (t >= NE) return;
    int a = idx_at(ei, 2*t,   g_ed64);
    int b = idx_at(ei, 2*t+1, g_ed64);
    atomicAdd(&g_deg[a], 1);
    atomicAdd(&g_deg[b], 1);
}

__global__ void k_scan() {  // single block, 1024 threads
    __shared__ int s[1024];
    int t = threadIdx.x;
    const int CH = 5;  // 1024*5 >= 5000
    int base = t * CH;
    int v[CH]; int tot = 0;
    #pragma unroll
    for (int i = 0; i < CH; i++) {
        int idx = base + i;
        v[i] = (idx < NN) ? g_deg[idx] : 0;
        tot += v[i];
    }
    s[t] = tot; __syncthreads();
    for (int ofs = 1; ofs < 1024; ofs <<= 1) {
        int val = s[t];
        int add = (t >= ofs) ? s[t - ofs] : 0;
        __syncthreads();
        s[t] = val + add;
        __syncthreads();
    }
    int run = s[t] - tot;  // exclusive prefix of this thread's chunk
    #pragma unroll
    for (int i = 0; i < CH; i++) {
        int idx = base + i;
        if (idx < NN) { g_off[idx] = run; run += v[i]; }
    }
    if (t == 1023) g_off[NN] = s[1023];
}

__global__ void k_fill(const void* __restrict__ ei) {
    int t = blockIdx.x * blockDim.x + threadIdx.x;
    if (t >= NE) return;
    int a = idx_at(ei, 2*t,   g_ed64);
    int b = idx_at(ei, 2*t+1, g_ed64);
    int pa = g_off[a] + atomicAdd(&g_cur[a], 1); g_adj[pa] = b;  // neighbor of a
    int pb = g_off[b] + atomicAdd(&g_cur[b], 1); g_adj[pb] = a;  // neighbor of b
}

// ---------------- layer-0 pieces ---------------------------------------------
__global__ void k_aggn() {
    int idx = blockIdx.x * blockDim.x + threadIdx.x;
    if (idx >= NN*XND) return;
    int n = idx / XND, d = idx % XND;
    int s0 = g_off[n], e0 = g_off[n+1];
    float s = 0.0f;
    for (int j = s0; j < e0; j++) s += g_xn[g_adj[j]*XND + d];
    g_aggn[idx] = s / fmaxf((float)(e0 - s0), 1.0f);
}

__global__ void k_pernode(const float* __restrict__ ws0, const float* __restrict__ wn0,
                          const float* __restrict__ b0) {
    int idx = blockIdx.x * blockDim.x + threadIdx.x;
    if (idx >= NN*HD) return;
    int n = idx >> 6, k = idx & 63;
    const float* xr = g_xn   + n*XND;
    const float* ar = g_aggn + n*XND;
    float acc = b0[k];
    #pragma unroll 4
    for (int d = 0; d < XND; d++)
        acc += xr[d]*ws0[d*HD + k] + ar[d]*wn0[d*HD + k];
    g_pernode[idx] = acc;
}

__global__ void k_cfg(const float* __restrict__ cf, const float* __restrict__ ws0,
                      const float* __restrict__ wn0) {
    int idx = blockIdx.x * blockDim.x + threadIdx.x;
    if (idx >= NC*HD) return;
    int c = idx >> 6, k = idx & 63;
    float s1 = 0.0f, s0v = 0.0f;
    #pragma unroll
    for (int d = 0; d < CFD; d++) {
        float cv = cf[c*CFD + d];
        float a  = ws0[(XND + d)*HD + k];
        float bq = wn0[(XND + d)*HD + k];
        s0v += cv * a;
        s1  += cv * (a + bq);
    }
    g_t0[idx] = s0v;
    g_t1[idx] = s1;
}

__global__ void k_h0() {
    int idx = blockIdx.x * blockDim.x + threadIdx.x;  // over NN*NC*16 float4
    if (idx >= NN*NC*16) return;
    int n = idx / (NC*16);
    int rem = idx % (NC*16);
    int c = rem >> 4, q = rem & 15;
    const float4* pn = (const float4*)g_pernode;
    const float4* tt = (g_deg[n] > 0) ? (const float4*)g_t1 : (const float4*)g_t0;
    float4 a = pn[n*16 + q];
    float4 b4 = tt[c*16 + q];
    a.x = fmaxf(a.x + b4.x, 0.0f);
    a.y = fmaxf(a.y + b4.y, 0.0f);
    a.z = fmaxf(a.z + b4.z, 0.0f);
    a.w = fmaxf(a.w + b4.w, 0.0f);
    ((float4*)g_h)[idx] = a;
}

// ---------------- edge aggregation for layers 1,2 ----------------------------
__global__ void __launch_bounds__(256) k_agg() {
    int n = blockIdx.x;
    int s0 = g_off[n], e0 = g_off[n+1];
    float inv = 1.0f / fmaxf((float)(e0 - s0), 1.0f);
    int t = threadIdx.x;
    float4 a0 = make_float4(0,0,0,0), a1 = make_float4(0,0,0,0);
    for (int j = s0; j < e0; j++) {
        const float4* row = (const float4*)(g_h + (size_t)g_adj[j]*NC*HD);
        float4 v0 = row[t], v1 = row[t + 256];
        a0.x += v0.x; a0.y += v0.y; a0.z += v0.z; a0.w += v0.w;
        a1.x += v1.x; a1.y += v1.y; a1.z += v1.z; a1.w += v1.w;
    }
    a0.x *= inv; a0.y *= inv; a0.z *= inv; a0.w *= inv;
    a1.x *= inv; a1.y *= inv; a1.z *= inv; a1.w *= inv;
    float4* out = (float4*)(g_agg + (size_t)n*NC*HD);
    out[t] = a0; out[t + 256] = a1;
}

// ---------------- layer update (in place): h = relu(h@Ws + agg@Wn + b) -------
__global__ void __launch_bounds__(256) k_layer(const float* __restrict__ wself,
                                               const float* __restrict__ wneigh,
                                               const float* __restrict__ bias) {
    __shared__ float sw[HD*HD], wn[HD*HD];
    __shared__ float hs[16*HD], as_[16*HD];
    __shared__ float sb[HD];
    int t = threadIdx.x;
    for (int i = t; i < HD*HD; i += 256) { sw[i] = wself[i]; wn[i] = wneigh[i]; }
    if (t < HD) sb[t] = bias[t];
    __syncthreads();
    int slot = t >> 4, kq = t & 15;
    const float4* swv = (const float4*)sw;
    const float4* wnv = (const float4*)wn;
    const int ntiles = (NN*NC) / 16;  // 10000
    for (int tile = blockIdx.x; tile < ntiles; tile += gridDim.x) {
        size_t rbase = (size_t)tile * 16;
        ((float4*)hs )[t] = ((const float4*)(g_h   + rbase*HD))[t];
        ((float4*)as_)[t] = ((const float4*)(g_agg + rbase*HD))[t];
        __syncthreads();
        float4 s = make_float4(sb[kq*4], sb[kq*4+1], sb[kq*4+2], sb[kq*4+3]);
        #pragma unroll 8
        for (int d = 0; d < HD; d++) {
            float hv = hs[slot*HD + d], av = as_[slot*HD + d];
            float4 w1 = swv[d*16 + kq], w2 = wnv[d*16 + kq];
            s.x += hv*w1.x + av*w2.x;
            s.y += hv*w1.y + av*w2.y;
            s.z += hv*w1.z + av*w2.z;
            s.w += hv*w1.w + av*w2.w;
        }
        float4 r = make_float4(fmaxf(s.x,0.f), fmaxf(s.y,0.f), fmaxf(s.z,0.f), fmaxf(s.w,0.f));
        ((float4*)g_h)[rbase*16 + t] = r;  // safe: rows loaded before first sync
        __syncthreads();
    }
}

// ---------------- skip projection + pooled sum over nodes --------------------
__global__ void __launch_bounds__(256) k_skip(const float* __restrict__ skw,
                                              const float* __restrict__ skb, int l) {
    __shared__ float sw[HD*HD];
    __shared__ float hs[16*HD];
    __shared__ float sb[HD];
    int t = threadIdx.x;
    int c = blockIdx.y;
    for (int i = t; i < HD*HD; i += 256) sw[i] = skw[l*HD*HD + i];
    if (t < HD) sb[t] = skb[l*HD + t];
    __syncthreads();
    int slot = t >> 4, kq = t & 15;
    const float4* swv = (const float4*)sw;
    float4 acc = make_float4(0,0,0,0);
    int nbase0 = blockIdx.x * 200;  // 25 blocks * 200 = 5000
    for (int g = 0; g < 13; g++) {  // 13*16 >= 200
        int node = nbase0 + g*16 + slot;
        bool valid = (node < nbase0 + 200);
        float4 hv4 = make_float4(0,0,0,0);
        if (valid) hv4 = ((const float4*)(g_h + ((size_t)node*NC + c)*HD))[kq];
        ((float4*)hs)[slot*16 + kq] = hv4;
        __syncthreads();
        float4 s = make_float4(sb[kq*4], sb[kq*4+1], sb[kq*4+2], sb[kq*4+3]);
        #pragma unroll 8
        for (int d = 0; d < HD; d++) {
            float hv = hs[slot*HD + d];
            float4 w = swv[d*16 + kq];
            s.x += hv*w.x; s.y += hv*w.y; s.z += hv*w.z; s.w += hv*w.w;
        }
        if (valid) {
            acc.x += fmaxf(s.x, 0.f);
            acc.y += fmaxf(s.y, 0.f);
            acc.z += fmaxf(s.z, 0.f);
            acc.w += fmaxf(s.w, 0.f);
        }
        __syncthreads();
    }
    // reduce across 16 slots
    ((float4*)hs)[slot*16 + kq] = acc;
    __syncthreads();
    for (int stride = 8; stride >= 1; stride >>= 1) {
        if (slot < stride) {
            float4 a = ((float4*)hs)[slot*16 + kq];
            float4 b4 = ((float4*)hs)[(slot+stride)*16 + kq];
            a.x += b4.x; a.y += b4.y; a.z += b4.z; a.w += b4.w;
            ((float4*)hs)[slot*16 + kq] = a;
        }
        __syncthreads();
    }
    if (slot == 0) {
        float4 a = ((float4*)hs)[kq];
        int base = c*POOLD + l*HD + kq*4;
        atomicAdd(&g_pool[base+0], a.x);
        atomicAdd(&g_pool[base+1], a.y);
        atomicAdd(&g_pool[base+2], a.z);
        atomicAdd(&g_pool[base+3], a.w);
    }
}

// ---------------- final MLP ---------------------------------------------------
__global__ void k_mlp(const float* __restrict__ p1w, const float* __restrict__ p1b,
                      const float* __restrict__ p2w, const float* __restrict__ p2b,
                      const float* __restrict__ p3w, const float* __restrict__ p3b,
                      float* __restrict__ out) {
    int c = blockIdx.x;
    int t = threadIdx.x;  // 128
    __shared__ float pr[POOLD], y1[128], y2[64];
    for (int i = t; i < POOLD; i += 128) pr[i] = g_pool[c*POOLD + i];
    __syncthreads();
    float s = p1b[t];
    #pragma unroll 4
    for (int d = 0; d < POOLD; d++) s += pr[d] * p1w[d*128 + t];
    y1[t] = fmaxf(s, 0.f);
    __syncthreads();
    if (t < 64) {
        float s2 = p2b[t];
        #pragma unroll 4
        for (int d = 0; d < 128; d++) s2 += y1[d] * p2w[d*64 + t];
        y2[t] = fmaxf(s2, 0.f);
    }
    __syncthreads();
    if (t == 0) {
        float s3 = p3b[0];
        for (int d = 0; d < 64; d++) s3 += y2[d] * p3w[d];
        out[c] = s3;
    }
}

// ---------------- launch ------------------------------------------------------
extern "C" void kernel_launch(void* const* d_in, const int* in_sizes, int n_in,
                              void* d_out, int out_size) {
    const float* nf     = (const float*)d_in[0];
    const void*  opc    = d_in[1];
    const void*  ei     = d_in[2];
    const float* cf     = (const float*)d_in[3];
    const float* op_emb = (const float*)d_in[4];
    const float* ws0    = (const float*)d_in[5];
    const float* wn0    = (const float*)d_in[6];
    const float* b0     = (const float*)d_in[7];
    const float* ws     = (const float*)d_in[8];   // (2,64,64)
    const float* wnn    = (const float*)d_in[9];   // (2,64,64)
    const float* bb     = (const float*)d_in[10];  // (2,64)
    const float* skw    = (const float*)d_in[11];  // (3,64,64)
    const float* skb    = (const float*)d_in[12];  // (3,64)
    const float* p1w    = (const float*)d_in[13];
    const float* p1b    = (const float*)d_in[14];
    const float* p2w    = (const float*)d_in[15];
    const float* p2b    = (const float*)d_in[16];
    const float* p3w    = (const float*)d_in[17];
    const float* p3b    = (const float*)d_in[18];
    float* out = (float*)d_out;

    k_init<<<24, 256>>>();
    k_detect<<<32, 256>>>(opc, ei);
    k_xn<<<(NN*XND + 255)/256, 256>>>(nf, opc, op_emb);
    k_deg<<<(NE + 255)/256, 256>>>(ei);
    k_scan<<<1, 1024>>>();
    k_fill<<<(NE + 255)/256, 256>>>(ei);
    k_aggn<<<(NN*XND + 255)/256, 256>>>();
    k_pernode<<<(NN*HD + 255)/256, 256>>>(ws0, wn0, b0);
    k_cfg<<<(NC*HD + 255)/256, 256>>>(cf, ws0, wn0);
    k_h0<<<(NN*NC*16 + 255)/256, 256>>>();
    k_skip<<<dim3(25, 32), 256>>>(skw, skb, 0);
    for (int l = 0; l < 2; l++) {
        k_agg<<<NN, 256>>>();
        k_layer<<<1184, 256>>>(ws + l*HD*HD, wnn + l*HD*HD, bb + l*HD);
        k_skip<<<dim3(25, 32), 256>>>(skw, skb, l + 1);
    }
    k_mlp<<<32, 128>>>(p1w, p1b, p2w, p2b, p3w, p3b, out);
}

// round 2
// speedup vs baseline: 1.6662x; 1.6662x over previous
#include <cuda_runtime.h>

#define NN   5000
#define NE   8000
#define NDIR (2*NE)
#define NC   32
#define HD   64
#define NF   140
#define OPD  8
#define XND  148   // 140 + 8
#define CFD  24
#define POOLD 192  // 3*64
#define ROWLEN (NC*HD)   // 2048 floats per node

// ---------------- device scratch (static: no runtime allocation) -------------
__device__ __align__(16) float g_xn[NN*XND];
__device__ __align__(16) float g_aggn[NN*XND];
__device__ __align__(16) float g_pernode[NN*HD];
__device__ __align__(16) float g_t1[NC*HD];
__device__ __align__(16) float g_t0[NC*HD];
__device__ __align__(16) float g_ha[(size_t)NN*ROWLEN];  // 40.96 MB
__device__ __align__(16) float g_hb[(size_t)NN*ROWLEN];  // 40.96 MB
__device__ int   g_deg[NN];
__device__ int   g_off[NN+1];
__device__ int   g_cur[NN];
__device__ int   g_adj[NDIR];
__device__ float g_pool[NC*POOLD];
__device__ int   g_op64, g_ed64;

__device__ __forceinline__ int idx_at(const void* p, int i, int is64) {
    if (is64) return (int)((const long long*)p)[i];
    return ((const int*)p)[i];
}

// ---------------- init / dtype detection ------------------------------------
__global__ void k_init() {
    int i = blockIdx.x * blockDim.x + threadIdx.x;
    if (i < NC*POOLD) g_pool[i] = 0.0f;
    if (i < NN) { g_deg[i] = 0; g_cur[i] = 0; }
    if (i == 0) { g_op64 = 1; g_ed64 = 1; }
}

__global__ void k_detect(const void* opc, const void* ei) {
    int i = blockIdx.x * blockDim.x + threadIdx.x;
    // If buffers are int64 (little-endian, small non-negative values), every
    // odd 32-bit word is 0. Random int32 data cannot satisfy this.
    if (i < 2500) { if (((const unsigned*)opc)[2*i+1] != 0u) g_op64 = 0; }
    if (i < 8000) { if (((const unsigned*)ei )[2*i+1] != 0u) g_ed64 = 0; }
}

// ---------------- node features + op embedding ------------------------------
__global__ void k_xn(const float* __restrict__ nf, const void* __restrict__ opc,
                     const float* __restrict__ op_emb) {
    int idx = blockIdx.x * blockDim.x + threadIdx.x;
    if (idx >= NN*XND) return;
    int n = idx / XND, d = idx % XND;
    if (d < NF) g_xn[idx] = nf[n*NF + d];
    else {
        int op = idx_at(opc, n, g_op64);
        g_xn[idx] = op_emb[op*OPD + (d - NF)];
    }
}

// ---------------- CSR build --------------------------------------------------
__global__ void k_deg(const void* __restrict__ ei) {
    int t = blockIdx.x * blockDim.x + threadIdx.x;
    if (t >= NE) return;
    int a = idx_at(ei, 2*t,   g_ed64);
    int b = idx_at(ei, 2*t+1, g_ed64);
    atomicAdd(&g_deg[a], 1);
    atomicAdd(&g_deg[b], 1);
}

__global__ void k_scan() {  // single block, 1024 threads
    __shared__ int s[1024];
    int t = threadIdx.x;
    const int CH = 5;  // 1024*5 >= 5000
    int base = t * CH;
    int v[CH]; int tot = 0;
    #pragma unroll
    for (int i = 0; i < CH; i++) {
        int idx = base + i;
        v[i] = (idx < NN) ? g_deg[idx] : 0;
        tot += v[i];
    }
    s[t] = tot; __syncthreads();
    for (int ofs = 1; ofs < 1024; ofs <<= 1) {
        int val = s[t];
        int add = (t >= ofs) ? s[t - ofs] : 0;
        __syncthreads();
        s[t] = val + add;
        __syncthreads();
    }
    int run = s[t] - tot;  // exclusive prefix of this thread's chunk
    #pragma unroll
    for (int i = 0; i < CH; i++) {
        int idx = base + i;
        if (idx < NN) { g_off[idx] = run; run += v[i]; }
    }
    if (t == 1023) g_off[NN] = s[1023];
}

__global__ void k_fill(const void* __restrict__ ei) {
    int t = blockIdx.x * blockDim.x + threadIdx.x;
    if (t >= NE) return;
    int a = idx_at(ei, 2*t,   g_ed64);
    int b = idx_at(ei, 2*t+1, g_ed64);
    int pa = g_off[a] + atomicAdd(&g_cur[a], 1); g_adj[pa] = b;
    int pb = g_off[b] + atomicAdd(&g_cur[b], 1); g_adj[pb] = a;
}

// ---------------- layer-0 pieces (node-space only, tiny) ---------------------
__global__ void k_aggn() {
    int idx = blockIdx.x * blockDim.x + threadIdx.x;
    if (idx >= NN*XND) return;
    int n = idx / XND, d = idx % XND;
    int s0 = g_off[n], e0 = g_off[n+1];
    float s = 0.0f;
    for (int j = s0; j < e0; j++) s += g_xn[g_adj[j]*XND + d];
    g_aggn[idx] = s / fmaxf((float)(e0 - s0), 1.0f);
}

__global__ void k_pernode(const float* __restrict__ ws0, const float* __restrict__ wn0,
                          const float* __restrict__ b0) {
    int idx = blockIdx.x * blockDim.x + threadIdx.x;
    if (idx >= NN*HD) return;
    int n = idx >> 6, k = idx & 63;
    const float* xr = g_xn   + n*XND;
    const float* ar = g_aggn + n*XND;
    float acc = b0[k];
    #pragma unroll 4
    for (int d = 0; d < XND; d++)
        acc += xr[d]*ws0[d*HD + k] + ar[d]*wn0[d*HD + k];
    g_pernode[idx] = acc;
}

__global__ void k_cfg(const float* __restrict__ cf, const float* __restrict__ ws0,
                      const float* __restrict__ wn0) {
    int idx = blockIdx.x * blockDim.x + threadIdx.x;
    if (idx >= NC*HD) return;
    int c = idx >> 6, k = idx & 63;
    float s1 = 0.0f, s0v = 0.0f;
    #pragma unroll
    for (int d = 0; d < CFD; d++) {
        float cv = cf[c*CFD + d];
        float a  = ws0[(XND + d)*HD + k];
        float bq = wn0[(XND + d)*HD + k];
        s0v += cv * a;
        s1  += cv * (a + bq);
    }
    g_t0[idx] = s0v;
    g_t1[idx] = s1;
}

// =============== fused h0 assembly + skip0 + pool ============================
// smem layout (floats): ssk[4096] t0[2048] t1[2048] hs[2048] kb[64]
__global__ void __launch_bounds__(256) k_h0skip(const float* __restrict__ skw,
                                                const float* __restrict__ skb) {
    extern __shared__ float sm[];
    float* ssk = sm;
    float* t0s = sm + 4096;
    float* t1s = sm + 6144;
    float* hs  = sm + 8192;
    float* kb  = sm + 10240;
    int t = threadIdx.x;
    for (int i = t; i < HD*HD; i += 256) ssk[i] = skw[i];
    for (int i = t; i < NC*HD; i += 256) { t0s[i] = g_t0[i]; t1s[i] = g_t1[i]; }
    if (t < HD) kb[t] = skb[t];
    __syncthreads();

    int slot = t >> 4, kq = t & 15;
    const float4* skv = (const float4*)ssk;
    float4 kbv = ((const float4*)kb)[kq];
    float4 pool0 = make_float4(0,0,0,0), pool1 = make_float4(0,0,0,0);

    for (int node = blockIdx.x; node < NN; node += gridDim.x) {
        const float4* tsel = (g_deg[node] > 0) ? (const float4*)t1s : (const float4*)t0s;
        float4 p = ((const float4*)(g_pernode + node*HD))[kq];
        float4 a = tsel[slot*16 + kq];
        float4 b = tsel[(slot+16)*16 + kq];
        float4 r0 = make_float4(fmaxf(p.x+a.x,0.f), fmaxf(p.y+a.y,0.f),
                                fmaxf(p.z+a.z,0.f), fmaxf(p.w+a.w,0.f));
        float4 r1 = make_float4(fmaxf(p.x+b.x,0.f), fmaxf(p.y+b.y,0.f),
                                fmaxf(p.z+b.z,0.f), fmaxf(p.w+b.w,0.f));
        float4* out = (float4*)(g_ha + (size_t)node*ROWLEN);
        out[t] = r0; out[t+256] = r1;
        ((float4*)hs)[t] = r0; ((float4*)hs)[t+256] = r1;
        __syncthreads();
        float4 s0v = kbv, s1v = kbv;
        #pragma unroll 8
        for (int d = 0; d < HD; d++) {
            float hv0 = hs[slot*HD + d];
            float hv1 = hs[(slot+16)*HD + d];
            float4 w = skv[d*16 + kq];
            s0v.x += hv0*w.x; s0v.y += hv0*w.y; s0v.z += hv0*w.z; s0v.w += hv0*w.w;
            s1v.x += hv1*w.x; s1v.y += hv1*w.y; s1v.z += hv1*w.z; s1v.w += hv1*w.w;
        }
        pool0.x += fmaxf(s0v.x,0.f); pool0.y += fmaxf(s0v.y,0.f);
        pool0.z += fmaxf(s0v.z,0.f); pool0.w += fmaxf(s0v.w,0.f);
        pool1.x += fmaxf(s1v.x,0.f); pool1.y += fmaxf(s1v.y,0.f);
        pool1.z += fmaxf(s1v.z,0.f); pool1.w += fmaxf(s1v.w,0.f);
        __syncthreads();
    }
    int b0i = slot*POOLD + kq*4;           // layer 0, config=slot
    int b1i = (slot+16)*POOLD + kq*4;      // config=slot+16
    atomicAdd(&g_pool[b0i+0], pool0.x); atomicAdd(&g_pool[b0i+1], pool0.y);
    atomicAdd(&g_pool[b0i+2], pool0.z); atomicAdd(&g_pool[b0i+3], pool0.w);
    atomicAdd(&g_pool[b1i+0], pool1.x); atomicAdd(&g_pool[b1i+1], pool1.y);
    atomicAdd(&g_pool[b1i+2], pool1.z); atomicAdd(&g_pool[b1i+3], pool1.w);
}

// =============== fused gather + dual GEMM + skip + pool ======================
// smem (floats): ws[4096] wn[4096] ssk[4096] hs[2048] as[2048] sb[64] kb[64]
__global__ void __launch_bounds__(256) k_layer_fused(
        const float* __restrict__ hold, float* __restrict__ hnew,
        const float* __restrict__ wself, const float* __restrict__ wneigh,
        const float* __restrict__ bias,
        const float* __restrict__ skw, const float* __restrict__ skb, int l) {
    extern __shared__ float sm[];
    float* sws = sm;
    float* swn = sm + 4096;
    float* ssk = sm + 8192;
    float* hs  = sm + 12288;
    float* as_ = sm + 14336;
    float* sb  = sm + 16384;
    float* kb  = sm + 16448;
    int t = threadIdx.x;
    for (int i = t; i < HD*HD; i += 256) {
        sws[i] = wself[i]; swn[i] = wneigh[i]; ssk[i] = skw[i];
    }
    if (t < HD) { sb[t] = bias[t]; kb[t] = skb[t]; }
    __syncthreads();

    int slot = t >> 4, kq = t & 15;
    const float4* wsv = (const float4*)sws;
    const float4* wnv = (const float4*)swn;
    const float4* skv = (const float4*)ssk;
    float4 sbv = ((const float4*)sb)[kq];
    float4 kbv = ((const float4*)kb)[kq];
    float4 pool0 = make_float4(0,0,0,0), pool1 = make_float4(0,0,0,0);

    for (int node = blockIdx.x; node < NN; node += gridDim.x) {
        int s0 = g_off[node], e0 = g_off[node+1];
        float inv = 1.0f / fmaxf((float)(e0 - s0), 1.0f);
        // own tile
        const float4* own = (const float4*)(hold + (size_t)node*ROWLEN);
        ((float4*)hs)[t] = own[t];
        ((float4*)hs)[t+256] = own[t+256];
        // gather neighbors (mean)
        float4 a0 = make_float4(0,0,0,0), a1 = make_float4(0,0,0,0);
        for (int j = s0; j < e0; j++) {
            const float4* row = (const float4*)(hold + (size_t)g_adj[j]*ROWLEN);
            float4 v0 = row[t], v1 = row[t+256];
            a0.x += v0.x; a0.y += v0.y; a0.z += v0.z; a0.w += v0.w;
            a1.x += v1.x; a1.y += v1.y; a1.z += v1.z; a1.w += v1.w;
        }
        a0.x *= inv; a0.y *= inv; a0.z *= inv; a0.w *= inv;
        a1.x *= inv; a1.y *= inv; a1.z *= inv; a1.w *= inv;
        ((float4*)as_)[t] = a0;
        ((float4*)as_)[t+256] = a1;
        __syncthreads();

        // dual GEMM: rows (configs) slot and slot+16, cols kq*4..kq*4+3
        float4 s0v = sbv, s1v = sbv;
        #pragma unroll 8
        for (int d = 0; d < HD; d++) {
            float hv0 = hs[slot*HD + d],      av0 = as_[slot*HD + d];
            float hv1 = hs[(slot+16)*HD + d], av1 = as_[(slot+16)*HD + d];
            float4 w1 = wsv[d*16 + kq], w2 = wnv[d*16 + kq];
            s0v.x += hv0*w1.x + av0*w2.x;
            s0v.y += hv0*w1.y + av0*w2.y;
            s0v.z += hv0*w1.z + av0*w2.z;
            s0v.w += hv0*w1.w + av0*w2.w;
            s1v.x += hv1*w1.x + av1*w2.x;
            s1v.y += hv1*w1.y + av1*w2.y;
            s1v.z += hv1*w1.z + av1*w2.z;
            s1v.w += hv1*w1.w + av1*w2.w;
        }
        float4 r0 = make_float4(fmaxf(s0v.x,0.f), fmaxf(s0v.y,0.f),
                                fmaxf(s0v.z,0.f), fmaxf(s0v.w,0.f));
        float4 r1 = make_float4(fmaxf(s1v.x,0.f), fmaxf(s1v.y,0.f),
                                fmaxf(s1v.z,0.f), fmaxf(s1v.w,0.f));
        float4* out = (float4*)(hnew + (size_t)node*ROWLEN);
        out[slot*16 + kq]      = r0;
        out[(slot+16)*16 + kq] = r1;
        __syncthreads();                    // everyone done reading hs
        ((float4*)hs)[slot*16 + kq]      = r0;
        ((float4*)hs)[(slot+16)*16 + kq] = r1;
        __syncthreads();

        // skip GEMM on fresh rows
        float4 k0 = kbv, k1 = kbv;
        #pragma unroll 8
        for (int d = 0; d < HD; d++) {
            float hv0 = hs[slot*HD + d];
            float hv1 = hs[(slot+16)*HD + d];
            float4 w = skv[d*16 + kq];
            k0.x += hv0*w.x; k0.y += hv0*w.y; k0.z += hv0*w.z; k0.w += hv0*w.w;
            k1.x += hv1*w.x; k1.y += hv1*w.y; k1.z += hv1*w.z; k1.w += hv1*w.w;
        }
        pool0.x += fmaxf(k0.x,0.f); pool0.y += fmaxf(k0.y,0.f);
        pool0.z += fmaxf(k0.z,0.f); pool0.w += fmaxf(k0.w,0.f);
        pool1.x += fmaxf(k1.x,0.f); pool1.y += fmaxf(k1.y,0.f);
        pool1.z += fmaxf(k1.z,0.f); pool1.w += fmaxf(k1.w,0.f);
        __syncthreads();
    }
    int b0i = slot*POOLD + l*HD + kq*4;
    int b1i = (slot+16)*POOLD + l*HD + kq*4;
    atomicAdd(&g_pool[b0i+0], pool0.x); atomicAdd(&g_pool[b0i+1], pool0.y);
    atomicAdd(&g_pool[b0i+2], pool0.z); atomicAdd(&g_pool[b0i+3], pool0.w);
    atomicAdd(&g_pool[b1i+0], pool1.x); atomicAdd(&g_pool[b1i+1], pool1.y);
    atomicAdd(&g_pool[b1i+2], pool1.z); atomicAdd(&g_pool[b1i+3], pool1.w);
}

// ---------------- final MLP ---------------------------------------------------
__global__ void k_mlp(const float* __restrict__ p1w, const float* __restrict__ p1b,
                      const float* __restrict__ p2w, const float* __restrict__ p2b,
                      const float* __restrict__ p3w, const float* __restrict__ p3b,
                      float* __restrict__ out) {
    int c = blockIdx.x;
    int t = threadIdx.x;  // 128
    __shared__ float pr[POOLD], y1[128], y2[64];
    for (int i = t; i < POOLD; i += 128) pr[i] = g_pool[c*POOLD + i];
    __syncthreads();
    float s = p1b[t];
    #pragma unroll 4
    for (int d = 0; d < POOLD; d++) s += pr[d] * p1w[d*128 + t];
    y1[t] = fmaxf(s, 0.f);
    __syncthreads();
    if (t < 64) {
        float s2 = p2b[t];
        #pragma unroll 4
        for (int d = 0; d < 128; d++) s2 += y1[d] * p2w[d*64 + t];
        y2[t] = fmaxf(s2, 0.f);
    }
    __syncthreads();
    if (t == 0) {
        float s3 = p3b[0];
        for (int d = 0; d < 64; d++) s3 += y2[d] * p3w[d];
        out[c] = s3;
    }
}

// ---------------- launch ------------------------------------------------------
extern "C" void kernel_launch(void* const* d_in, const int* in_sizes, int n_in,
                              void* d_out, int out_size) {
    const float* nf     = (const float*)d_in[0];
    const void*  opc    = d_in[1];
    const void*  ei     = d_in[2];
    const float* cf     = (const float*)d_in[3];
    const float* op_emb = (const float*)d_in[4];
    const float* ws0    = (const float*)d_in[5];
    const float* wn0    = (const float*)d_in[6];
    const float* b0     = (const float*)d_in[7];
    const float* ws     = (const float*)d_in[8];   // (2,64,64)
    const float* wnn    = (const float*)d_in[9];   // (2,64,64)
    const float* bb     = (const float*)d_in[10];  // (2,64)
    const float* skw    = (const float*)d_in[11];  // (3,64,64)
    const float* skb    = (const float*)d_in[12];  // (3,64)
    const float* p1w    = (const float*)d_in[13];
    const float* p1b    = (const float*)d_in[14];
    const float* p2w    = (const float*)d_in[15];
    const float* p2b    = (const float*)d_in[16];
    const float* p3w    = (const float*)d_in[17];
    const float* p3b    = (const float*)d_in[18];
    float* out = (float*)d_out;

    const int SMEM_L = 16512 * (int)sizeof(float);  // 66048 B
    const int SMEM_H = 10304 * (int)sizeof(float);  // 41216 B
    static int attr_done = 0;
    if (!attr_done) {
        cudaFuncSetAttribute(k_layer_fused,
                             cudaFuncAttributeMaxDynamicSharedMemorySize, SMEM_L);
        cudaFuncSetAttribute(k_h0skip,
                             cudaFuncAttributeMaxDynamicSharedMemorySize, SMEM_H);
        attr_done = 1;
    }

    k_init<<<24, 256>>>();
    k_detect<<<32, 256>>>(opc, ei);
    k_xn<<<(NN*XND + 255)/256, 256>>>(nf, opc, op_emb);
    k_deg<<<(NE + 255)/256, 256>>>(ei);
    k_scan<<<1, 1024>>>();
    k_fill<<<(NE + 255)/256, 256>>>(ei);
    k_aggn<<<(NN*XND + 255)/256, 256>>>();
    k_pernode<<<(NN*HD + 255)/256, 256>>>(ws0, wn0, b0);
    k_cfg<<<(NC*HD + 255)/256, 256>>>(cf, ws0, wn0);

    float* pha = nullptr; float* phb = nullptr;
    cudaGetSymbolAddress((void**)&pha, g_ha);
    cudaGetSymbolAddress((void**)&phb, g_hb);

    k_h0skip<<<444, 256, SMEM_H>>>(skw, skb);
    k_layer_fused<<<444, 256, SMEM_L>>>(pha, phb, ws, wnn, bb, skw + HD*HD,
                                        skb + HD, 1);
    k_layer_fused<<<444, 256, SMEM_L>>>(phb, pha, ws + HD*HD, wnn + HD*HD,
                                        bb + HD, skw + 2*HD*HD, skb + 2*HD, 2);
    k_mlp<<<32, 128>>>(p1w, p1b, p2w, p2b, p3w, p3b, out);
}

// round 3
// speedup vs baseline: 2.1511x; 1.2910x over previous
#include <cuda_runtime.h>

#define NN   5000
#define NE   8000
#define NDIR (2*NE)
#define NC   32
#define HD   64
#define NF   140
#define OPD  8
#define XND  148   // 140 + 8
#define CFD  24
#define POOLD 192  // 3*64
#define ROWLEN (NC*HD)   // 2048 floats per node

typedef unsigned long long ull;

__device__ __forceinline__ ull f2pack(float x, float y) {
    ull r; asm("mov.b64 %0,{%1,%2};" : "=l"(r) : "f"(x), "f"(y)); return r;
}
__device__ __forceinline__ ull fma2(ull a, ull b, ull c) {
    ull d; asm("fma.rn.f32x2 %0,%1,%2,%3;" : "=l"(d) : "l"(a), "l"(b), "l"(c)); return d;
}
__device__ __forceinline__ float2 f2unpack(ull v) {
    float lo, hi; asm("mov.b64 {%0,%1},%2;" : "=f"(lo), "=f"(hi) : "l"(v));
    float2 r; r.x = lo; r.y = hi; return r;
}

// ---------------- device scratch (static: no runtime allocation) -------------
__device__ __align__(16) float g_xn[NN*XND];
__device__ __align__(16) float g_aggn[NN*XND];
__device__ __align__(16) float g_pernode[NN*HD];
__device__ __align__(16) float g_t1[NC*HD];
__device__ __align__(16) float g_t0[NC*HD];
__device__ __align__(16) float g_ha[(size_t)NN*ROWLEN];  // 40.96 MB
__device__ __align__(16) float g_hb[(size_t)NN*ROWLEN];  // 40.96 MB
__device__ int   g_deg[NN];
__device__ int   g_off[NN+1];
__device__ int   g_cur[NN];
__device__ int   g_adj[NDIR];
__device__ float g_pool[NC*POOLD];
__device__ int   g_op64, g_ed64;

__device__ __forceinline__ int idx_at(const void* p, int i, int is64) {
    if (is64) return (int)((const long long*)p)[i];
    return ((const int*)p)[i];
}

// ---------------- init / dtype detection ------------------------------------
__global__ void k_init() {
    int i = blockIdx.x * blockDim.x + threadIdx.x;
    if (i < NC*POOLD) g_pool[i] = 0.0f;
    if (i < NN) { g_deg[i] = 0; g_cur[i] = 0; }
    if (i == 0) { g_op64 = 1; g_ed64 = 1; }
}

__global__ void k_detect(const void* opc, const void* ei) {
    int i = blockIdx.x * blockDim.x + threadIdx.x;
    if (i < 2500) { if (((const unsigned*)opc)[2*i+1] != 0u) g_op64 = 0; }
    if (i < 8000) { if (((const unsigned*)ei )[2*i+1] != 0u) g_ed64 = 0; }
}

// ---------------- node features + op embedding ------------------------------
__global__ void k_xn(const float* __restrict__ nf, const void* __restrict__ opc,
                     const float* __restrict__ op_emb) {
    int idx = blockIdx.x * blockDim.x + threadIdx.x;
    if (idx >= NN*XND) return;
    int n = idx / XND, d = idx % XND;
    if (d < NF) g_xn[idx] = nf[n*NF + d];
    else {
        int op = idx_at(opc, n, g_op64);
        g_xn[idx] = op_emb[op*OPD + (d - NF)];
    }
}

// ---------------- CSR build --------------------------------------------------
__global__ void k_deg(const void* __restrict__ ei) {
    int t = blockIdx.x * blockDim.x + threadIdx.x;
    if (t >= NE) return;
    int a = idx_at(ei, 2*t,   g_ed64);
    int b = idx_at(ei, 2*t+1, g_ed64);
    atomicAdd(&g_deg[a], 1);
    atomicAdd(&g_deg[b], 1);
}

__global__ void k_scan() {
    __shared__ int s[1024];
    int t = threadIdx.x;
    const int CH = 5;
    int base = t * CH;
    int v[CH]; int tot = 0;
    #pragma unroll
    for (int i = 0; i < CH; i++) {
        int idx = base + i;
        v[i] = (idx < NN) ? g_deg[idx] : 0;
        tot += v[i];
    }
    s[t] = tot; __syncthreads();
    for (int ofs = 1; ofs < 1024; ofs <<= 1) {
        int val = s[t];
        int add = (t >= ofs) ? s[t - ofs] : 0;
        __syncthreads();
        s[t] = val + add;
        __syncthreads();
    }
    int run = s[t] - tot;
    #pragma unroll
    for (int i = 0; i < CH; i++) {
        int idx = base + i;
        if (idx < NN) { g_off[idx] = run; run += v[i]; }
    }
    if (t == 1023) g_off[NN] = s[1023];
}

__global__ void k_fill(const void* __restrict__ ei) {
    int t = blockIdx.x * blockDim.x + threadIdx.x;
    if (t >= NE) return;
    int a = idx_at(ei, 2*t,   g_ed64);
    int b = idx_at(ei, 2*t+1, g_ed64);
    int pa = g_off[a] + atomicAdd(&g_cur[a], 1); g_adj[pa] = b;
    int pb = g_off[b] + atomicAdd(&g_cur[b], 1); g_adj[pb] = a;
}

// ---------------- node-space aggregation (148-dim) ---------------------------
__global__ void k_aggn() {
    int idx = blockIdx.x * blockDim.x + threadIdx.x;
    if (idx >= NN*XND) return;
    int n = idx / XND, d = idx % XND;
    int s0 = g_off[n], e0 = g_off[n+1];
    float s = 0.0f;
    for (int j = s0; j < e0; j++) s += g_xn[g_adj[j]*XND + d];
    g_aggn[idx] = s / fmaxf((float)(e0 - s0), 1.0f);
}

// ---------------- per-node layer-0 GEMM (smem-tiled, f32x2) -------------------
// smem: ws0s[9472] wn0s[9472] xs[4736] as[4736] = 28416 floats
__global__ void __launch_bounds__(256) k_pernode2(const float* __restrict__ ws0,
                                                  const float* __restrict__ wn0,
                                                  const float* __restrict__ b0) {
    extern __shared__ float sm[];
    float* ws0s = sm;
    float* wn0s = sm + 9472;
    float* xs   = sm + 18944;
    float* as_  = sm + 23680;
    int t = threadIdx.x;
    int tile = blockIdx.x;                 // 157 tiles of 32 nodes
    for (int i = t; i < XND*HD; i += 256) { ws0s[i] = ws0[i]; wn0s[i] = wn0[i]; }
    for (int i = t; i < 32*37; i += 256) {
        int node = tile*32 + i/37, q = i % 37;
        float4 xv = make_float4(0,0,0,0), av = make_float4(0,0,0,0);
        if (node < NN) {
            xv = ((const float4*)g_xn)[node*37 + q];
            av = ((const float4*)g_aggn)[node*37 + q];
        }
        ((float4*)xs)[i] = xv;
        ((float4*)as_)[i] = av;
    }
    __syncthreads();

    int rg = t >> 4, cg = t & 15;          // 16 rowgroups x 16 colgroups
    float4 b4 = *(const float4*)(b0 + cg*4);
    ull acc[2][2];
    acc[0][0] = f2pack(b4.x, b4.y); acc[0][1] = f2pack(b4.z, b4.w);
    acc[1][0] = acc[0][0];          acc[1][1] = acc[0][1];

    for (int dc = 0; dc < XND; dc += 4) {
        float4 x0 = *(const float4*)(xs  + (rg*2+0)*XND + dc);
        float4 x1 = *(const float4*)(xs  + (rg*2+1)*XND + dc);
        float4 a0 = *(const float4*)(as_ + (rg*2+0)*XND + dc);
        float4 a1 = *(const float4*)(as_ + (rg*2+1)*XND + dc);
        #pragma unroll
        for (int i = 0; i < 4; i++) {
            const ull* w1p = (const ull*)(ws0s + (dc+i)*HD + cg*4);
            const ull* w2p = (const ull*)(wn0s + (dc+i)*HD + cg*4);
            ull w1lo = w1p[0], w1hi = w1p[1];
            ull w2lo = w2p[0], w2hi = w2p[1];
            {
                float hx = ((const float*)&x0)[i], ax = ((const float*)&a0)[i];
                ull hb = f2pack(hx,hx), ab = f2pack(ax,ax);
                acc[0][0] = fma2(hb, w1lo, acc[0][0]);
                acc[0][0] = fma2(ab, w2lo, acc[0][0]);
                acc[0][1] = fma2(hb, w1hi, acc[0][1]);
                acc[0][1] = fma2(ab, w2hi, acc[0][1]);
            }
            {
                float hx = ((const float*)&x1)[i], ax = ((const float*)&a1)[i];
                ull hb = f2pack(hx,hx), ab = f2pack(ax,ax);
                acc[1][0] = fma2(hb, w1lo, acc[1][0]);
                acc[1][0] = fma2(ab, w2lo, acc[1][0]);
                acc[1][1] = fma2(hb, w1hi, acc[1][1]);
                acc[1][1] = fma2(ab, w2hi, acc[1][1]);
            }
        }
    }
    #pragma unroll
    for (int n = 0; n < 2; n++) {
        int node = tile*32 + rg*2 + n;
        if (node < NN) {
            float2 lo = f2unpack(acc[n][0]), hi = f2unpack(acc[n][1]);
            ((float4*)(g_pernode + node*HD))[cg] = make_float4(lo.x, lo.y, hi.x, hi.y);
        }
    }
}

// ---------------- config-space layer-0 terms ---------------------------------
__global__ void k_cfg(const float* __restrict__ cf, const float* __restrict__ ws0,
                      const float* __restrict__ wn0) {
    int idx = blockIdx.x * blockDim.x + threadIdx.x;
    if (idx >= NC*HD) return;
    int c = idx >> 6, k = idx & 63;
    float s1 = 0.0f, s0v = 0.0f;
    #pragma unroll
    for (int d = 0; d < CFD; d++) {
        float cv = cf[c*CFD + d];
        float a  = ws0[(XND + d)*HD + k];
        float bq = wn0[(XND + d)*HD + k];
        s0v += cv * a;
        s1  += cv * (a + bq);
    }
    g_t0[idx] = s0v;
    g_t1[idx] = s1;
}

// =============== fused h0 assembly + skip0 + pool ============================
// smem: ssk[4096] t0s[2048] t1s[2048] hs[2x2048] kb[64] = 12352 floats
__global__ void __launch_bounds__(256, 2) k_h0skip(const float* __restrict__ skw,
                                                   const float* __restrict__ skb) {
    extern __shared__ float sm[];
    float* ssk = sm;
    float* t0s = sm + 4096;
    float* t1s = sm + 6144;
    int t = threadIdx.x;
    for (int i = t; i < HD*HD; i += 256) ssk[i] = skw[i];
    for (int i = t; i < NC*HD; i += 256) { t0s[i] = g_t0[i]; t1s[i] = g_t1[i]; }
    if (t < HD) sm[12288 + t] = skb[t];
    __syncthreads();

    int half = t >> 7, wt = t & 127;
    int rg = wt >> 4, cg = wt & 15;
    float* hsn = sm + 8192 + half*2048;
    float4 kb4 = *(const float4*)(sm + 12288 + cg*4);
    ull kb2lo = f2pack(kb4.x, kb4.y), kb2hi = f2pack(kb4.z, kb4.w);
    float pool[4][4];
    #pragma unroll
    for (int r = 0; r < 4; r++)
        #pragma unroll
        for (int c = 0; c < 4; c++) pool[r][c] = 0.0f;

    for (int base = blockIdx.x*2; base < NN; base += gridDim.x*2) {
        int node = base + half;
        __syncthreads();
        const float* tsel = (g_deg[node] > 0) ? t1s : t0s;
        float4 p = ((const float4*)(g_pernode + node*HD))[cg];
        #pragma unroll
        for (int r = 0; r < 4; r++) {
            float4 tv = *(const float4*)(tsel + (rg*4+r)*HD + cg*4);
            float4 rr = make_float4(fmaxf(p.x+tv.x,0.f), fmaxf(p.y+tv.y,0.f),
                                    fmaxf(p.z+tv.z,0.f), fmaxf(p.w+tv.w,0.f));
            *(float4*)(hsn + (rg*4+r)*HD + cg*4) = rr;
            *(float4*)(g_ha + (size_t)node*ROWLEN + (rg*4+r)*HD + cg*4) = rr;
        }
        __syncthreads();
        // skip GEMM rows rg*4..+3, cols cg*4..+3
        ull ka[4][2];
        #pragma unroll
        for (int r = 0; r < 4; r++) { ka[r][0] = kb2lo; ka[r][1] = kb2hi; }
        for (int dc = 0; dc < HD; dc += 4) {
            float4 h0 = *(const float4*)(hsn + (rg*4+0)*HD + dc);
            float4 h1 = *(const float4*)(hsn + (rg*4+1)*HD + dc);
            float4 h2 = *(const float4*)(hsn + (rg*4+2)*HD + dc);
            float4 h3 = *(const float4*)(hsn + (rg*4+3)*HD + dc);
            #pragma unroll
            for (int i = 0; i < 4; i++) {
                const ull* wp = (const ull*)(ssk + (dc+i)*HD + cg*4);
                ull wlo = wp[0], whi = wp[1];
                ull hb;
                hb = f2pack(((const float*)&h0)[i], ((const float*)&h0)[i]);
                ka[0][0] = fma2(hb, wlo, ka[0][0]); ka[0][1] = fma2(hb, whi, ka[0][1]);
                hb = f2pack(((const float*)&h1)[i], ((const float*)&h1)[i]);
                ka[1][0] = fma2(hb, wlo, ka[1][0]); ka[1][1] = fma2(hb, whi, ka[1][1]);
                hb = f2pack(((const float*)&h2)[i], ((const float*)&h2)[i]);
                ka[2][0] = fma2(hb, wlo, ka[2][0]); ka[2][1] = fma2(hb, whi, ka[2][1]);
                hb = f2pack(((const float*)&h3)[i], ((const float*)&h3)[i]);
                ka[3][0] = fma2(hb, wlo, ka[3][0]); ka[3][1] = fma2(hb, whi, ka[3][1]);
            }
        }
        #pragma unroll
        for (int r = 0; r < 4; r++) {
            float2 lo = f2unpack(ka[r][0]), hi = f2unpack(ka[r][1]);
            pool[r][0] += fmaxf(lo.x, 0.f); pool[r][1] += fmaxf(lo.y, 0.f);
            pool[r][2] += fmaxf(hi.x, 0.f); pool[r][3] += fmaxf(hi.y, 0.f);
        }
    }
    __syncthreads();
    if (half == 1) {
        #pragma unroll
        for (int r = 0; r < 4; r++)
            #pragma unroll
            for (int c = 0; c < 4; c++) sm[8192 + wt*16 + r*4 + c] = pool[r][c];
    }
    __syncthreads();
    if (half == 0) {
        #pragma unroll
        for (int r = 0; r < 4; r++)
            #pragma unroll
            for (int c = 0; c < 4; c++) {
                float v = pool[r][c] + sm[8192 + wt*16 + r*4 + c];
                atomicAdd(&g_pool[(rg*4+r)*POOLD + cg*4 + c], v);
            }
    }
}

// =============== fused gather + dual GEMM + skip + pool ======================
// smem: sws[4096] swn[4096] ssk[4096] hs[2x2048] as[2x2048] sb[64] kb[64]
__global__ void __launch_bounds__(256, 2) k_layer_fused(
        const float* __restrict__ hold, float* __restrict__ hnew,
        const float* __restrict__ wself, const float* __restrict__ wneigh,
        const float* __restrict__ bias,
        const float* __restrict__ skw, const float* __restrict__ skb, int l) {
    extern __shared__ float sm[];
    float* sws = sm;
    float* swn = sm + 4096;
    float* ssk = sm + 8192;
    int t = threadIdx.x;
    for (int i = t; i < HD*HD; i += 256) {
        sws[i] = wself[i]; swn[i] = wneigh[i]; ssk[i] = skw[i];
    }
    if (t < HD) { sm[20480 + t] = bias[t]; sm[20544 + t] = skb[t]; }
    __syncthreads();

    int half = t >> 7, wt = t & 127;
    int rg = wt >> 4, cg = wt & 15;
    float* hsn = sm + 12288 + half*2048;
    float* asn = sm + 16384 + half*2048;
    float4 sb4 = *(const float4*)(sm + 20480 + cg*4);
    float4 kb4 = *(const float4*)(sm + 20544 + cg*4);
    ull sb2lo = f2pack(sb4.x, sb4.y), sb2hi = f2pack(sb4.z, sb4.w);
    ull kb2lo = f2pack(kb4.x, kb4.y), kb2hi = f2pack(kb4.z, kb4.w);
    float pool[4][4];
    #pragma unroll
    for (int r = 0; r < 4; r++)
        #pragma unroll
        for (int c = 0; c < 4; c++) pool[r][c] = 0.0f;

    for (int base = blockIdx.x*2; base < NN; base += gridDim.x*2) {
        int node = base + half;
        __syncthreads();  // prior iteration's skip reads done
        // ---- gather: own row + mean of neighbors
        int s0 = g_off[node], e0 = g_off[node+1];
        float inv = 1.0f / fmaxf((float)(e0 - s0), 1.0f);
        const float4* own = (const float4*)(hold + (size_t)node*ROWLEN);
        float4* h4 = (float4*)hsn;
        float4* a4 = (float4*)asn;
        float4 ac0 = make_float4(0,0,0,0), ac1 = ac0, ac2 = ac0, ac3 = ac0;
        h4[wt]     = own[wt];
        h4[wt+128] = own[wt+128];
        h4[wt+256] = own[wt+256];
        h4[wt+384] = own[wt+384];
        for (int j = s0; j < e0; j++) {
            const float4* row = (const float4*)(hold + (size_t)g_adj[j]*ROWLEN);
            float4 v0 = row[wt], v1 = row[wt+128], v2 = row[wt+256], v3 = row[wt+384];
            ac0.x += v0.x; ac0.y += v0.y; ac0.z += v0.z; ac0.w += v0.w;
            ac1.x += v1.x; ac1.y += v1.y; ac1.z += v1.z; ac1.w += v1.w;
            ac2.x += v2.x; ac2.y += v2.y; ac2.z += v2.z; ac2.w += v2.w;
            ac3.x += v3.x; ac3.y += v3.y; ac3.z += v3.z; ac3.w += v3.w;
        }
        ac0.x*=inv; ac0.y*=inv; ac0.z*=inv; ac0.w*=inv;
        ac1.x*=inv; ac1.y*=inv; ac1.z*=inv; ac1.w*=inv;
        ac2.x*=inv; ac2.y*=inv; ac2.z*=inv; ac2.w*=inv;
        ac3.x*=inv; ac3.y*=inv; ac3.z*=inv; ac3.w*=inv;
        a4[wt] = ac0; a4[wt+128] = ac1; a4[wt+256] = ac2; a4[wt+384] = ac3;
        __syncthreads();

        // ---- dual GEMM: 4 rows (configs rg*4..+3) x 4 cols (cg*4..+3)
        ull acc[4][2];
        #pragma unroll
        for (int r = 0; r < 4; r++) { acc[r][0] = sb2lo; acc[r][1] = sb2hi; }
        for (int dc = 0; dc < HD; dc += 4) {
            float4 h0 = *(const float4*)(hsn + (rg*4+0)*HD + dc);
            float4 h1 = *(const float4*)(hsn + (rg*4+1)*HD + dc);
            float4 h2 = *(const float4*)(hsn + (rg*4+2)*HD + dc);
            float4 h3 = *(const float4*)(hsn + (rg*4+3)*HD + dc);
            float4 a0 = *(const float4*)(asn + (rg*4+0)*HD + dc);
            float4 a1 = *(const float4*)(asn + (rg*4+1)*HD + dc);
            float4 a2 = *(const float4*)(asn + (rg*4+2)*HD + dc);
            float4 a3 = *(const float4*)(asn + (rg*4+3)*HD + dc);
            #pragma unroll
            for (int i = 0; i < 4; i++) {
                const ull* w1p = (const ull*)(sws + (dc+i)*HD + cg*4);
                const ull* w2p = (const ull*)(swn + (dc+i)*HD + cg*4);
                ull w1lo = w1p[0], w1hi = w1p[1];
                ull w2lo = w2p[0], w2hi = w2p[1];
                ull hb, ab;
                hb = f2pack(((const float*)&h0)[i], ((const float*)&h0)[i]);
                ab = f2pack(((const float*)&a0)[i], ((const float*)&a0)[i]);
                acc[0][0] = fma2(hb, w1lo, acc[0][0]);
                acc[0][0] = fma2(ab, w2lo, acc[0][0]);
                acc[0][1] = fma2(hb, w1hi, acc[0][1]);
                acc[0][1] = fma2(ab, w2hi, acc[0][1]);
                hb = f2pack(((const float*)&h1)[i], ((const float*)&h1)[i]);
                ab = f2pack(((const float*)&a1)[i], ((const float*)&a1)[i]);
                acc[1][0] = fma2(hb, w1lo, acc[1][0]);
                acc[1][0] = fma2(ab, w2lo, acc[1][0]);
                acc[1][1] = fma2(hb, w1hi, acc[1][1]);
                acc[1][1] = fma2(ab, w2hi, acc[1][1]);
                hb = f2pack(((const float*)&h2)[i], ((const float*)&h2)[i]);
                ab = f2pack(((const float*)&a2)[i], ((const float*)&a2)[i]);
                acc[2][0] = fma2(hb, w1lo, acc[2][0]);
                acc[2][0] = fma2(ab, w2lo, acc[2][0]);
                acc[2][1] = fma2(hb, w1hi, acc[2][1]);
                acc[2][1] = fma2(ab, w2hi, acc[2][1]);
                hb = f2pack(((const float*)&h3)[i], ((const float*)&h3)[i]);
                ab = f2pack(((const float*)&a3)[i], ((const float*)&a3)[i]);
                acc[3][0] = fma2(hb, w1lo, acc[3][0]);
                acc[3][0] = fma2(ab, w2lo, acc[3][0]);
                acc[3][1] = fma2(hb, w1hi, acc[3][1]);
                acc[3][1] = fma2(ab, w2hi, acc[3][1]);
            }
        }
        __syncthreads();  // all reads of old hs/as done
        #pragma unroll
        for (int r = 0; r < 4; r++) {
            float2 lo = f2unpack(acc[r][0]), hi = f2unpack(acc[r][1]);
            float4 rr = make_float4(fmaxf(lo.x,0.f), fmaxf(lo.y,0.f),
                                    fmaxf(hi.x,0.f), fmaxf(hi.y,0.f));
            *(float4*)(hsn + (rg*4+r)*HD + cg*4) = rr;
            *(float4*)(hnew + (size_t)node*ROWLEN + (rg*4+r)*HD + cg*4) = rr;
        }
        __syncthreads();

        // ---- skip GEMM on fresh h
        ull ka[4][2];
        #pragma unroll
        for (int r = 0; r < 4; r++) { ka[r][0] = kb2lo; ka[r][1] = kb2hi; }
        for (int dc = 0; dc < HD; dc += 4) {
            float4 h0 = *(const float4*)(hsn + (rg*4+0)*HD + dc);
            float4 h1 = *(const float4*)(hsn + (rg*4+1)*HD + dc);
            float4 h2 = *(const float4*)(hsn + (rg*4+2)*HD + dc);
            float4 h3 = *(const float4*)(hsn + (rg*4+3)*HD + dc);
            #pragma unroll
            for (int i = 0; i < 4; i++) {
                const ull* wp = (const ull*)(ssk + (dc+i)*HD + cg*4);
                ull wlo = wp[0], whi = wp[1];
                ull hb;
                hb = f2pack(((const float*)&h0)[i], ((const float*)&h0)[i]);
                ka[0][0] = fma2(hb, wlo, ka[0][0]); ka[0][1] = fma2(hb, whi, ka[0][1]);
                hb = f2pack(((const float*)&h1)[i], ((const float*)&h1)[i]);
                ka[1][0] = fma2(hb, wlo, ka[1][0]); ka[1][1] = fma2(hb, whi, ka[1][1]);
                hb = f2pack(((const float*)&h2)[i], ((const float*)&h2)[i]);
                ka[2][0] = fma2(hb, wlo, ka[2][0]); ka[2][1] = fma2(hb, whi, ka[2][1]);
                hb = f2pack(((const float*)&h3)[i], ((const float*)&h3)[i]);
                ka[3][0] = fma2(hb, wlo, ka[3][0]); ka[3][1] = fma2(hb, whi, ka[3][1]);
            }
        }
        #pragma unroll
        for (int r = 0; r < 4; r++) {
            float2 lo = f2unpack(ka[r][0]), hi = f2unpack(ka[r][1]);
            pool[r][0] += fmaxf(lo.x, 0.f); pool[r][1] += fmaxf(lo.y, 0.f);
            pool[r][2] += fmaxf(hi.x, 0.f); pool[r][3] += fmaxf(hi.y, 0.f);
        }
    }
    __syncthreads();
    if (half == 1) {
        #pragma unroll
        for (int r = 0; r < 4; r++)
            #pragma unroll
            for (int c = 0; c < 4; c++) sm[12288 + wt*16 + r*4 + c] = pool[r][c];
    }
    __syncthreads();
    if (half == 0) {
        #pragma unroll
        for (int r = 0; r < 4; r++)
            #pragma unroll
            for (int c = 0; c < 4; c++) {
                float v = pool[r][c] + sm[12288 + wt*16 + r*4 + c];
                atomicAdd(&g_pool[(rg*4+r)*POOLD + l*HD + cg*4 + c], v);
            }
    }
}

// ---------------- final MLP ---------------------------------------------------
__global__ void k_mlp(const float* __restrict__ p1w, const float* __restrict__ p1b,
                      const float* __restrict__ p2w, const float* __restrict__ p2b,
                      const float* __restrict__ p3w, const float* __restrict__ p3b,
                      float* __restrict__ out) {
    int c = blockIdx.x;
    int t = threadIdx.x;  // 128
    __shared__ float pr[POOLD], y1[128], y2[64];
    for (int i = t; i < POOLD; i += 128) pr[i] = g_pool[c*POOLD + i];
    __syncthreads();
    float s = p1b[t];
    #pragma unroll 4
    for (int d = 0; d < POOLD; d++) s += pr[d] * p1w[d*128 + t];
    y1[t] = fmaxf(s, 0.f);
    __syncthreads();
    if (t < 64) {
        float s2 = p2b[t];
        #pragma unroll 4
        for (int d = 0; d < 128; d++) s2 += y1[d] * p2w[d*64 + t];
        y2[t] = fmaxf(s2, 0.f);
    }
    __syncthreads();
    if (t == 0) {
        float s3 = p3b[0];
        for (int d = 0; d < 64; d++) s3 += y2[d] * p3w[d];
        out[c] = s3;
    }
}

// ---------------- launch ------------------------------------------------------
extern "C" void kernel_launch(void* const* d_in, const int* in_sizes, int n_in,
                              void* d_out, int out_size) {
    const float* nf     = (const float*)d_in[0];
    const void*  opc    = d_in[1];
    const void*  ei     = d_in[2];
    const float* cf     = (const float*)d_in[3];
    const float* op_emb = (const float*)d_in[4];
    const float* ws0    = (const float*)d_in[5];
    const float* wn0    = (const float*)d_in[6];
    const float* b0     = (const float*)d_in[7];
    const float* ws     = (const float*)d_in[8];
    const float* wnn    = (const float*)d_in[9];
    const float* bb     = (const float*)d_in[10];
    const float* skw    = (const float*)d_in[11];
    const float* skb    = (const float*)d_in[12];
    const float* p1w    = (const float*)d_in[13];
    const float* p1b    = (const float*)d_in[14];
    const float* p2w    = (const float*)d_in[15];
    const float* p2b    = (const float*)d_in[16];
    const float* p3w    = (const float*)d_in[17];
    const float* p3b    = (const float*)d_in[18];
    float* out = (float*)d_out;

    const int SMEM_L  = 20608 * (int)sizeof(float);  // 82432 B
    const int SMEM_H  = 12352 * (int)sizeof(float);  // 49408 B
    const int SMEM_PN = 28416 * (int)sizeof(float);  // 113664 B
    cudaFuncSetAttribute(k_layer_fused,
                         cudaFuncAttributeMaxDynamicSharedMemorySize, SMEM_L);
    cudaFuncSetAttribute(k_h0skip,
                         cudaFuncAttributeMaxDynamicSharedMemorySize, SMEM_H);
    cudaFuncSetAttribute(k_pernode2,
                         cudaFuncAttributeMaxDynamicSharedMemorySize, SMEM_PN);

    float* pha = nullptr; float* phb = nullptr;
    cudaGetSymbolAddress((void**)&pha, g_ha);
    cudaGetSymbolAddress((void**)&phb, g_hb);

    k_init<<<24, 256>>>();
    k_detect<<<32, 256>>>(opc, ei);
    k_xn<<<(NN*XND + 255)/256, 256>>>(nf, opc, op_emb);
    k_deg<<<(NE + 255)/256, 256>>>(ei);
    k_scan<<<1, 1024>>>();
    k_fill<<<(NE + 255)/256, 256>>>(ei);
    k_aggn<<<(NN*XND + 255)/256, 256>>>();
    k_pernode2<<<157, 256, SMEM_PN>>>(ws0, wn0, b0);
    k_cfg<<<(NC*HD + 255)/256, 256>>>(cf, ws0, wn0);

    k_h0skip<<<296, 256, SMEM_H>>>(skw, skb);
    k_layer_fused<<<296, 256, SMEM_L>>>(pha, phb, ws, wnn, bb,
                                        skw + HD*HD, skb + HD, 1);
    k_layer_fused<<<296, 256, SMEM_L>>>(phb, pha, ws + HD*HD, wnn + HD*HD,
                                        bb + HD, skw + 2*HD*HD, skb + 2*HD, 2);
    k_mlp<<<32, 128>>>(p1w, p1b, p2w, p2b, p3w, p3b, out);
}

// round 4
// speedup vs baseline: 2.3635x; 1.0987x over previous
#include <cuda_runtime.h>

#define NN   5000
#define NE   8000
#define NDIR (2*NE)
#define NC   32
#define HD   64
#define NF   140
#define OPD  8
#define XND  148
#define CFD  24
#define POOLD 192
#define ROWLEN (NC*HD)   // 2048

typedef unsigned long long ull;

__device__ __forceinline__ ull f2pack(float x, float y) {
    ull r; asm("mov.b64 %0,{%1,%2};" : "=l"(r) : "f"(x), "f"(y)); return r;
}
__device__ __forceinline__ ull fma2(ull a, ull b, ull c) {
    ull d; asm("fma.rn.f32x2 %0,%1,%2,%3;" : "=l"(d) : "l"(a), "l"(b), "l"(c)); return d;
}
__device__ __forceinline__ float2 f2unpack(ull v) {
    float lo, hi; asm("mov.b64 {%0,%1},%2;" : "=f"(lo), "=f"(hi) : "l"(v));
    float2 r; r.x = lo; r.y = hi; return r;
}

// ---------------- device scratch ---------------------------------------------
__device__ __align__(16) float g_xn[NN*XND];
__device__ __align__(16) float g_aggn[NN*XND];
__device__ __align__(16) float g_pernode[NN*HD];
__device__ __align__(16) float g_t1[NC*HD];
__device__ __align__(16) float g_t0[NC*HD];
__device__ __align__(16) float g_ha[(size_t)NN*ROWLEN];
__device__ __align__(16) float g_hb[(size_t)NN*ROWLEN];
__device__ int   g_deg[NN];
__device__ int   g_off[NN+1];
__device__ int   g_cur[NN];
__device__ int   g_adj[NDIR];
__device__ float g_pool[NC*POOLD];
// dtype flags: static-init to 1 (int64); detection only ever clears to 0, so the
// value is monotonic and input-determined -> deterministic across graph replays.
__device__ int g_op64 = 1, g_ed64 = 1;

__device__ __forceinline__ int idx_at(const void* p, int i, int is64) {
    if (is64) return (int)((const long long*)p)[i];
    return ((const int*)p)[i];
}

// ---------------- pre: zero state + dtype detection ---------------------------
__global__ void k_pre(const void* opc, const void* ei) {
    int i = blockIdx.x * blockDim.x + threadIdx.x;   // 8192 threads
    if (i < NC*POOLD) g_pool[i] = 0.0f;
    if (i < NN) { g_deg[i] = 0; g_cur[i] = 0; }
    if (i < 2500) { if (((const unsigned*)opc)[2*i+1] != 0u) g_op64 = 0; }
    if (i < 8000) { if (((const unsigned*)ei )[2*i+1] != 0u) g_ed64 = 0; }
}

// ---------------- xn assembly + degree count ----------------------------------
__global__ void k_xn_deg(const float* __restrict__ nf, const void* __restrict__ opc,
                         const float* __restrict__ op_emb, const void* __restrict__ ei) {
    int idx = blockIdx.x * blockDim.x + threadIdx.x;
    if (idx < NN*XND) {
        int n = idx / XND, d = idx % XND;
        if (d < NF) g_xn[idx] = nf[n*NF + d];
        else {
            int op = idx_at(opc, n, g_op64);
            g_xn[idx] = op_emb[op*OPD + (d - NF)];
        }
    }
    if (idx < NE) {
        int a = idx_at(ei, 2*idx,   g_ed64);
        int b = idx_at(ei, 2*idx+1, g_ed64);
        atomicAdd(&g_deg[a], 1);
        atomicAdd(&g_deg[b], 1);
    }
}

// ---------------- scan (block 0) + cfg terms (blocks 1,2) ---------------------
__global__ void k_scan_cfg(const float* __restrict__ cf, const float* __restrict__ ws0,
                           const float* __restrict__ wn0) {
    if (blockIdx.x == 0) {
        __shared__ int s[1024];
        int t = threadIdx.x;
        const int CH = 5;
        int base = t * CH;
        int v[CH]; int tot = 0;
        #pragma unroll
        for (int i = 0; i < CH; i++) {
            int idx = base + i;
            v[i] = (idx < NN) ? g_deg[idx] : 0;
            tot += v[i];
        }
        s[t] = tot; __syncthreads();
        for (int ofs = 1; ofs < 1024; ofs <<= 1) {
            int val = s[t];
            int add = (t >= ofs) ? s[t - ofs] : 0;
            __syncthreads();
            s[t] = val + add;
            __syncthreads();
        }
        int run = s[t] - tot;
        #pragma unroll
        for (int i = 0; i < CH; i++) {
            int idx = base + i;
            if (idx < NN) { g_off[idx] = run; run += v[i]; }
        }
        if (t == 1023) g_off[NN] = s[1023];
    } else {
        int idx = (blockIdx.x - 1) * 1024 + threadIdx.x;
        if (idx >= NC*HD) return;
        int c = idx >> 6, k = idx & 63;
        float s1 = 0.0f, s0v = 0.0f;
        #pragma unroll
        for (int d = 0; d < CFD; d++) {
            float cv = cf[c*CFD + d];
            float a  = ws0[(XND + d)*HD + k];
            float bq = wn0[(XND + d)*HD + k];
            s0v += cv * a;
            s1  += cv * (a + bq);
        }
        g_t0[idx] = s0v;
        g_t1[idx] = s1;
    }
}

__global__ void k_fill(const void* __restrict__ ei) {
    int t = blockIdx.x * blockDim.x + threadIdx.x;
    if (t >= NE) return;
    int a = idx_at(ei, 2*t,   g_ed64);
    int b = idx_at(ei, 2*t+1, g_ed64);
    int pa = g_off[a] + atomicAdd(&g_cur[a], 1); g_adj[pa] = b;
    int pb = g_off[b] + atomicAdd(&g_cur[b], 1); g_adj[pb] = a;
}

// ---------------- node-space aggregation (148-dim) -----------------------------
__global__ void k_aggn() {
    int idx = blockIdx.x * blockDim.x + threadIdx.x;
    if (idx >= NN*XND) return;
    int n = idx / XND, d = idx % XND;
    int s0 = g_off[n], e0 = g_off[n+1];
    float s = 0.0f;
    for (int j = s0; j < e0; j++) s += g_xn[g_adj[j]*XND + d];
    g_aggn[idx] = s / fmaxf((float)(e0 - s0), 1.0f);
}

// ---------------- per-node layer-0 GEMM (smem-tiled, f32x2) --------------------
__global__ void __launch_bounds__(256) k_pernode2(const float* __restrict__ ws0,
                                                  const float* __restrict__ wn0,
                                                  const float* __restrict__ b0) {
    extern __shared__ float sm[];
    float* ws0s = sm;
    float* wn0s = sm + 9472;
    float* xs   = sm + 18944;
    float* as_  = sm + 23680;
    int t = threadIdx.x;
    int tile = blockIdx.x;
    for (int i = t; i < XND*HD; i += 256) { ws0s[i] = ws0[i]; wn0s[i] = wn0[i]; }
    for (int i = t; i < 32*37; i += 256) {
        int node = tile*32 + i/37, q = i % 37;
        float4 xv = make_float4(0,0,0,0), av = make_float4(0,0,0,0);
        if (node < NN) {
            xv = ((const float4*)g_xn)[node*37 + q];
            av = ((const float4*)g_aggn)[node*37 + q];
        }
        ((float4*)xs)[i] = xv;
        ((float4*)as_)[i] = av;
    }
    __syncthreads();

    int rg = t >> 4, cg = t & 15;
    float4 b4 = *(const float4*)(b0 + cg*4);
    ull acc[2][2];
    acc[0][0] = f2pack(b4.x, b4.y); acc[0][1] = f2pack(b4.z, b4.w);
    acc[1][0] = acc[0][0];          acc[1][1] = acc[0][1];

    for (int dc = 0; dc < XND; dc += 4) {
        float4 x0 = *(const float4*)(xs  + (rg*2+0)*XND + dc);
        float4 x1 = *(const float4*)(xs  + (rg*2+1)*XND + dc);
        float4 a0 = *(const float4*)(as_ + (rg*2+0)*XND + dc);
        float4 a1 = *(const float4*)(as_ + (rg*2+1)*XND + dc);
        #pragma unroll
        for (int i = 0; i < 4; i++) {
            const ull* w1p = (const ull*)(ws0s + (dc+i)*HD + cg*4);
            const ull* w2p = (const ull*)(wn0s + (dc+i)*HD + cg*4);
            ull w1lo = w1p[0], w1hi = w1p[1];
            ull w2lo = w2p[0], w2hi = w2p[1];
            {
                float hx = ((const float*)&x0)[i], ax = ((const float*)&a0)[i];
                ull hb = f2pack(hx,hx), ab = f2pack(ax,ax);
                acc[0][0] = fma2(hb, w1lo, acc[0][0]);
                acc[0][0] = fma2(ab, w2lo, acc[0][0]);
                acc[0][1] = fma2(hb, w1hi, acc[0][1]);
                acc[0][1] = fma2(ab, w2hi, acc[0][1]);
            }
            {
                float hx = ((const float*)&x1)[i], ax = ((const float*)&a1)[i];
                ull hb = f2pack(hx,hx), ab = f2pack(ax,ax);
                acc[1][0] = fma2(hb, w1lo, acc[1][0]);
                acc[1][0] = fma2(ab, w2lo, acc[1][0]);
                acc[1][1] = fma2(hb, w1hi, acc[1][1]);
                acc[1][1] = fma2(ab, w2hi, acc[1][1]);
            }
        }
    }
    #pragma unroll
    for (int n = 0; n < 2; n++) {
        int node = tile*32 + rg*2 + n;
        if (node < NN) {
            float2 lo = f2unpack(acc[n][0]), hi = f2unpack(acc[n][1]);
            ((float4*)(g_pernode + node*HD))[cg] = make_float4(lo.x, lo.y, hi.x, hi.y);
        }
    }
}

// ---------------- flat h0 assembly (no skip here anymore) ----------------------
__global__ void k_h0() {
    int idx = blockIdx.x * blockDim.x + threadIdx.x;   // NN*NC*16 float4s
    if (idx >= NN*NC*16) return;
    int node = idx >> 9;
    int rem = idx & 511;
    int c = rem >> 4, q = rem & 15;
    const float4* tt = (g_deg[node] > 0) ? (const float4*)g_t1 : (const float4*)g_t0;
    float4 p = ((const float4*)g_pernode)[node*16 + q];
    float4 tv = tt[c*16 + q];
    float4 r = make_float4(fmaxf(p.x+tv.x,0.f), fmaxf(p.y+tv.y,0.f),
                           fmaxf(p.z+tv.z,0.f), fmaxf(p.w+tv.w,0.f));
    ((float4*)g_ha)[idx] = r;
}

// =============== fused gather + triple GEMM (dual + skip-on-input) =============
// smem floats: sws[4096] swn[4096] ssp[4096] sso[4096] hs[4096] as[4096] b[192]
template<int DO_OUT>
__global__ void __launch_bounds__(256, 2) k_layer2(
        const float* __restrict__ hold, float* __restrict__ hnew,
        const float* __restrict__ wself, const float* __restrict__ wneigh,
        const float* __restrict__ bias,
        const float* __restrict__ skwp, const float* __restrict__ skbp, int lp,
        const float* __restrict__ skwo, const float* __restrict__ skbo, int lo) {
    extern __shared__ float sm[];
    float* sws = sm;
    float* swn = sm + 4096;
    float* ssp = sm + 8192;
    float* sso = sm + 12288;
    float* hsb = sm + 16384;
    float* asb = sm + 20480;
    float* bds = sm + 24576;
    float* bps = sm + 24640;
    float* bos = sm + 24704;
    int t = threadIdx.x;
    for (int i = t; i < HD*HD; i += 256) {
        sws[i] = wself[i]; swn[i] = wneigh[i]; ssp[i] = skwp[i];
        if (DO_OUT) sso[i] = skwo[i];
    }
    if (t < HD) {
        bds[t] = bias[t]; bps[t] = skbp[t];
        if (DO_OUT) bos[t] = skbo[t];
    }
    __syncthreads();

    int half = t >> 7, wt = t & 127;
    int rg = wt >> 4, cg = wt & 15;
    float* hsn = hsb + half*2048;
    float* asn = asb + half*2048;
    ull bdlo = f2pack(bds[cg*4], bds[cg*4+1]), bdhi = f2pack(bds[cg*4+2], bds[cg*4+3]);
    ull bplo = f2pack(bps[cg*4], bps[cg*4+1]), bphi = f2pack(bps[cg*4+2], bps[cg*4+3]);
    ull bolo = 0, bohi = 0;
    if (DO_OUT) { bolo = f2pack(bos[cg*4], bos[cg*4+1]); bohi = f2pack(bos[cg*4+2], bos[cg*4+3]); }
    float poolp[4][4], poolo[4][4];
    #pragma unroll
    for (int r = 0; r < 4; r++)
        #pragma unroll
        for (int c = 0; c < 4; c++) { poolp[r][c] = 0.0f; poolo[r][c] = 0.0f; }

    for (int base = blockIdx.x*2; base < NN; base += gridDim.x*2) {
        int node = base + half;
        __syncthreads();                 // smem free from prior iteration
        // ---- stage own row + mean-gather neighbors
        int s0 = g_off[node], e0 = g_off[node+1];
        float inv = 1.0f / fmaxf((float)(e0 - s0), 1.0f);
        const float4* own = (const float4*)(hold + (size_t)node*ROWLEN);
        float4* h4 = (float4*)hsn;
        float4* a4 = (float4*)asn;
        h4[wt]     = own[wt];
        h4[wt+128] = own[wt+128];
        h4[wt+256] = own[wt+256];
        h4[wt+384] = own[wt+384];
        float4 ac0 = make_float4(0,0,0,0), ac1 = ac0, ac2 = ac0, ac3 = ac0;
        for (int j = s0; j < e0; j++) {
            const float4* row = (const float4*)(hold + (size_t)g_adj[j]*ROWLEN);
            float4 v0 = row[wt], v1 = row[wt+128], v2 = row[wt+256], v3 = row[wt+384];
            ac0.x += v0.x; ac0.y += v0.y; ac0.z += v0.z; ac0.w += v0.w;
            ac1.x += v1.x; ac1.y += v1.y; ac1.z += v1.z; ac1.w += v1.w;
            ac2.x += v2.x; ac2.y += v2.y; ac2.z += v2.z; ac2.w += v2.w;
            ac3.x += v3.x; ac3.y += v3.y; ac3.z += v3.z; ac3.w += v3.w;
        }
        ac0.x*=inv; ac0.y*=inv; ac0.z*=inv; ac0.w*=inv;
        ac1.x*=inv; ac1.y*=inv; ac1.z*=inv; ac1.w*=inv;
        ac2.x*=inv; ac2.y*=inv; ac2.z*=inv; ac2.w*=inv;
        ac3.x*=inv; ac3.y*=inv; ac3.z*=inv; ac3.w*=inv;
        a4[wt] = ac0; a4[wt+128] = ac1; a4[wt+256] = ac2; a4[wt+384] = ac3;
        __syncthreads();

        // ---- combined: dual GEMM + skip-on-input, sharing h/a LDS
        ull accd[4][2], acck[4][2];
        #pragma unroll
        for (int r = 0; r < 4; r++) {
            accd[r][0] = bdlo; accd[r][1] = bdhi;
            acck[r][0] = bplo; acck[r][1] = bphi;
        }
        for (int dc = 0; dc < HD; dc += 4) {
            float4 h[4], a[4];
            #pragma unroll
            for (int r = 0; r < 4; r++) {
                h[r] = *(const float4*)(hsn + (rg*4+r)*HD + dc);
                a[r] = *(const float4*)(asn + (rg*4+r)*HD + dc);
            }
            #pragma unroll
            for (int i = 0; i < 4; i++) {
                const ull* w1p = (const ull*)(sws + (dc+i)*HD + cg*4);
                const ull* w2p = (const ull*)(swn + (dc+i)*HD + cg*4);
                const ull* wkp = (const ull*)(ssp + (dc+i)*HD + cg*4);
                ull w1lo = w1p[0], w1hi = w1p[1];
                ull w2lo = w2p[0], w2hi = w2p[1];
                ull wklo = wkp[0], wkhi = wkp[1];
                #pragma unroll
                for (int r = 0; r < 4; r++) {
                    float hx = ((const float*)&h[r])[i];
                    float ax = ((const float*)&a[r])[i];
                    ull hb = f2pack(hx, hx);
                    ull ab = f2pack(ax, ax);
                    accd[r][0] = fma2(hb, w1lo, accd[r][0]);
                    accd[r][0] = fma2(ab, w2lo, accd[r][0]);
                    accd[r][1] = fma2(hb, w1hi, accd[r][1]);
                    accd[r][1] = fma2(ab, w2hi, accd[r][1]);
                    acck[r][0] = fma2(hb, wklo, acck[r][0]);
                    acck[r][1] = fma2(hb, wkhi, acck[r][1]);
                }
            }
        }
        // dual result: relu -> gmem (no smem bounce); skip result -> pool regs
        float4 rr[4];
        #pragma unroll
        for (int r = 0; r < 4; r++) {
            float2 lo = f2unpack(accd[r][0]), hi = f2unpack(accd[r][1]);
            rr[r] = make_float4(fmaxf(lo.x,0.f), fmaxf(lo.y,0.f),
                                fmaxf(hi.x,0.f), fmaxf(hi.y,0.f));
            *(float4*)(hnew + (size_t)node*ROWLEN + (rg*4+r)*HD + cg*4) = rr[r];
            float2 klo = f2unpack(acck[r][0]), khi = f2unpack(acck[r][1]);
            poolp[r][0] += fmaxf(klo.x, 0.f); poolp[r][1] += fmaxf(klo.y, 0.f);
            poolp[r][2] += fmaxf(khi.x, 0.f); poolp[r][3] += fmaxf(khi.y, 0.f);
        }

        if (DO_OUT) {
            __syncthreads();             // all reads of hsn done
            #pragma unroll
            for (int r = 0; r < 4; r++)
                *(float4*)(hsn + (rg*4+r)*HD + cg*4) = rr[r];
            __syncthreads();
            ull acco[4][2];
            #pragma unroll
            for (int r = 0; r < 4; r++) { acco[r][0] = bolo; acco[r][1] = bohi; }
            for (int dc = 0; dc < HD; dc += 4) {
                float4 h[4];
                #pragma unroll
                for (int r = 0; r < 4; r++)
                    h[r] = *(const float4*)(hsn + (rg*4+r)*HD + dc);
                #pragma unroll
                for (int i = 0; i < 4; i++) {
                    const ull* wp = (const ull*)(sso + (dc+i)*HD + cg*4);
                    ull wlo = wp[0], whi = wp[1];
                    #pragma unroll
                    for (int r = 0; r < 4; r++) {
                        float hx = ((const float*)&h[r])[i];
                        ull hb = f2pack(hx, hx);
                        acco[r][0] = fma2(hb, wlo, acco[r][0]);
                        acco[r][1] = fma2(hb, whi, acco[r][1]);
                    }
                }
            }
            #pragma unroll
            for (int r = 0; r < 4; r++) {
                float2 lo = f2unpack(acco[r][0]), hi = f2unpack(acco[r][1]);
                poolo[r][0] += fmaxf(lo.x, 0.f); poolo[r][1] += fmaxf(lo.y, 0.f);
                poolo[r][2] += fmaxf(hi.x, 0.f); poolo[r][3] += fmaxf(hi.y, 0.f);
            }
        }
    }
    // ---- pool reduction (half1 -> smem, half0 adds + atomics)
    __syncthreads();
    if (half == 1) {
        #pragma unroll
        for (int r = 0; r < 4; r++)
            #pragma unroll
            for (int c = 0; c < 4; c++) {
                hsb[wt*16 + r*4 + c] = poolp[r][c];
                if (DO_OUT) asb[wt*16 + r*4 + c] = poolo[r][c];
            }
    }
    __syncthreads();
    if (half == 0) {
        #pragma unroll
        for (int r = 0; r < 4; r++)
            #pragma unroll
            for (int c = 0; c < 4; c++) {
                float v = poolp[r][c] + hsb[wt*16 + r*4 + c];
                atomicAdd(&g_pool[(rg*4+r)*POOLD + lp*HD + cg*4 + c], v);
                if (DO_OUT) {
                    float w = poolo[r][c] + asb[wt*16 + r*4 + c];
                    atomicAdd(&g_pool[(rg*4+r)*POOLD + lo*HD + cg*4 + c], w);
                }
            }
    }
}

// ---------------- final MLP ----------------------------------------------------
__global__ void k_mlp(const float* __restrict__ p1w, const float* __restrict__ p1b,
                      const float* __restrict__ p2w, const float* __restrict__ p2b,
                      const float* __restrict__ p3w, const float* __restrict__ p3b,
                      float* __restrict__ out) {
    int c = blockIdx.x;
    int t = threadIdx.x;  // 128
    __shared__ float pr[POOLD], y1[128], y2[64];
    for (int i = t; i < POOLD; i += 128) pr[i] = g_pool[c*POOLD + i];
    __syncthreads();
    float s = p1b[t];
    #pragma unroll 4
    for (int d = 0; d < POOLD; d++) s += pr[d] * p1w[d*128 + t];
    y1[t] = fmaxf(s, 0.f);
    __syncthreads();
    if (t < 64) {
        float s2 = p2b[t];
        #pragma unroll 4
        for (int d = 0; d < 128; d++) s2 += y1[d] * p2w[d*64 + t];
        y2[t] = fmaxf(s2, 0.f);
    }
    __syncthreads();
    if (t == 0) {
        float s3 = p3b[0];
        for (int d = 0; d < 64; d++) s3 += y2[d] * p3w[d];
        out[c] = s3;
    }
}

// ---------------- launch -------------------------------------------------------
extern "C" void kernel_launch(void* const* d_in, const int* in_sizes, int n_in,
                              void* d_out, int out_size) {
    const float* nf     = (const float*)d_in[0];
    const void*  opc    = d_in[1];
    const void*  ei     = d_in[2];
    const float* cf     = (const float*)d_in[3];
    const float* op_emb = (const float*)d_in[4];
    const float* ws0    = (const float*)d_in[5];
    const float* wn0    = (const float*)d_in[6];
    const float* b0     = (const float*)d_in[7];
    const float* ws     = (const float*)d_in[8];
    const float* wnn    = (const float*)d_in[9];
    const float* bb     = (const float*)d_in[10];
    const float* skw    = (const float*)d_in[11];
    const float* skb    = (const float*)d_in[12];
    const float* p1w    = (const float*)d_in[13];
    const float* p1b    = (const float*)d_in[14];
    const float* p2w    = (const float*)d_in[15];
    const float* p2b    = (const float*)d_in[16];
    const float* p3w    = (const float*)d_in[17];
    const float* p3b    = (const float*)d_in[18];
    float* out = (float*)d_out;

    const int SMEM_L  = 24768 * (int)sizeof(float);  // 99072 B
    const int SMEM_PN = 28416 * (int)sizeof(float);  // 113664 B
    cudaFuncSetAttribute(k_layer2<0>,
                         cudaFuncAttributeMaxDynamicSharedMemorySize, SMEM_L);
    cudaFuncSetAttribute(k_layer2<1>,
                         cudaFuncAttributeMaxDynamicSharedMemorySize, SMEM_L);
    cudaFuncSetAttribute(k_pernode2,
                         cudaFuncAttributeMaxDynamicSharedMemorySize, SMEM_PN);

    float* pha = nullptr; float* phb = nullptr;
    cudaGetSymbolAddress((void**)&pha, g_ha);
    cudaGetSymbolAddress((void**)&phb, g_hb);

    k_pre<<<32, 256>>>(opc, ei);
    k_xn_deg<<<(NN*XND + 255)/256, 256>>>(nf, opc, op_emb, ei);
    k_scan_cfg<<<3, 1024>>>(cf, ws0, wn0);
    k_fill<<<(NE + 255)/256, 256>>>(ei);
    k_aggn<<<(NN*XND + 255)/256, 256>>>();
    k_pernode2<<<157, 256, SMEM_PN>>>(ws0, wn0, b0);
    k_h0<<<(NN*NC*16 + 255)/256, 256>>>();

    k_layer2<0><<<296, 256, SMEM_L>>>(pha, phb, ws, wnn, bb,
                                      skw, skb, 0,
                                      nullptr, nullptr, 0);
    k_layer2<1><<<296, 256, SMEM_L>>>(phb, pha, ws + HD*HD, wnn + HD*HD, bb + HD,
                                      skw + HD*HD, skb + HD, 1,
                                      skw + 2*HD*HD, skb + 2*HD, 2);
    k_mlp<<<32, 128>>>(p1w, p1b, p2w, p2b, p3w, p3b, out);
}

// round 5
// speedup vs baseline: 2.8148x; 1.1909x over previous
#include <cuda_runtime.h>

#define NN   5000
#define NE   8000
#define NDIR (2*NE)
#define NC   32
#define HD   64
#define NF   140
#define OPD  8
#define XND  148
#define CFD  24
#define POOLD 192
#define ROWLEN (NC*HD)   // 2048

typedef unsigned long long ull;

__device__ __forceinline__ ull f2pack(float x, float y) {
    ull r; asm("mov.b64 %0,{%1,%2};" : "=l"(r) : "f"(x), "f"(y)); return r;
}
__device__ __forceinline__ ull fma2(ull a, ull b, ull c) {
    ull d; asm("fma.rn.f32x2 %0,%1,%2,%3;" : "=l"(d) : "l"(a), "l"(b), "l"(c)); return d;
}
__device__ __forceinline__ float2 f2unpack(ull v) {
    float lo, hi; asm("mov.b64 {%0,%1},%2;" : "=f"(lo), "=f"(hi) : "l"(v));
    float2 r; r.x = lo; r.y = hi; return r;
}
__device__ __forceinline__ float4 relu4(float4 a) {
    return make_float4(fmaxf(a.x,0.f), fmaxf(a.y,0.f), fmaxf(a.z,0.f), fmaxf(a.w,0.f));
}

// ---------------- device scratch ---------------------------------------------
__device__ __align__(16) float g_xn[NN*XND];
__device__ __align__(16) float g_pernode[NN*HD];
__device__ __align__(16) float g_t1[NC*HD];
__device__ __align__(16) float g_t0[NC*HD];
__device__ __align__(16) float g_h1[(size_t)NN*ROWLEN];  // 40.96 MB
__device__ int   g_deg[NN];
__device__ int   g_off[NN+1];
__device__ int   g_cur[NN];
__device__ int   g_adj[NDIR];
__device__ float g_pool[NC*POOLD];
// dtype flags: static-init 1; detection only clears -> monotone, input-determined.
__device__ int g_op64 = 1, g_ed64 = 1;

__device__ __forceinline__ int idx_at(const void* p, int i, int is64) {
    if (is64) return (int)((const long long*)p)[i];
    return ((const int*)p)[i];
}

// ---------------- pre: zero state + dtype detection ---------------------------
__global__ void k_pre(const void* opc, const void* ei) {
    int i = blockIdx.x * blockDim.x + threadIdx.x;
    if (i < NC*POOLD) g_pool[i] = 0.0f;
    if (i < NN) { g_deg[i] = 0; g_cur[i] = 0; }
    if (i < 2500) { if (((const unsigned*)opc)[2*i+1] != 0u) g_op64 = 0; }
    if (i < 8000) { if (((const unsigned*)ei )[2*i+1] != 0u) g_ed64 = 0; }
}

// ---------------- xn assembly + degree count ----------------------------------
__global__ void k_xn_deg(const float* __restrict__ nf, const void* __restrict__ opc,
                         const float* __restrict__ op_emb, const void* __restrict__ ei) {
    int idx = blockIdx.x * blockDim.x + threadIdx.x;
    if (idx < NN*XND) {
        int n = idx / XND, d = idx % XND;
        if (d < NF) g_xn[idx] = nf[n*NF + d];
        else {
            int op = idx_at(opc, n, g_op64);
            g_xn[idx] = op_emb[op*OPD + (d - NF)];
        }
    }
    if (idx < NE) {
        int a = idx_at(ei, 2*idx,   g_ed64);
        int b = idx_at(ei, 2*idx+1, g_ed64);
        atomicAdd(&g_deg[a], 1);
        atomicAdd(&g_deg[b], 1);
    }
}

// ---------------- scan (block 0) + cfg terms (blocks 1,2) ---------------------
__global__ void k_scan_cfg(const float* __restrict__ cf, const float* __restrict__ ws0,
                           const float* __restrict__ wn0) {
    if (blockIdx.x == 0) {
        __shared__ int s[1024];
        int t = threadIdx.x;
        const int CH = 5;
        int base = t * CH;
        int v[CH]; int tot = 0;
        #pragma unroll
        for (int i = 0; i < CH; i++) {
            int idx = base + i;
            v[i] = (idx < NN) ? g_deg[idx] : 0;
            tot += v[i];
        }
        s[t] = tot; __syncthreads();
        for (int ofs = 1; ofs < 1024; ofs <<= 1) {
            int val = s[t];
            int add = (t >= ofs) ? s[t - ofs] : 0;
            __syncthreads();
            s[t] = val + add;
            __syncthreads();
        }
        int run = s[t] - tot;
        #pragma unroll
        for (int i = 0; i < CH; i++) {
            int idx = base + i;
            if (idx < NN) { g_off[idx] = run; run += v[i]; }
        }
        if (t == 1023) g_off[NN] = s[1023];
    } else {
        int idx = (blockIdx.x - 1) * 1024 + threadIdx.x;
        if (idx >= NC*HD) return;
        int c = idx >> 6, k = idx & 63;
        float s1 = 0.0f, s0v = 0.0f;
        #pragma unroll
        for (int d = 0; d < CFD; d++) {
            float cv = cf[c*CFD + d];
            float a  = ws0[(XND + d)*HD + k];
            float bq = wn0[(XND + d)*HD + k];
            s0v += cv * a;
            s1  += cv * (a + bq);
        }
        g_t0[idx] = s0v;
        g_t1[idx] = s1;
    }
}

__global__ void k_fill(const void* __restrict__ ei) {
    int t = blockIdx.x * blockDim.x + threadIdx.x;
    if (t >= NE) return;
    int a = idx_at(ei, 2*t,   g_ed64);
    int b = idx_at(ei, 2*t+1, g_ed64);
    int pa = g_off[a] + atomicAdd(&g_cur[a], 1); g_adj[pa] = b;
    int pb = g_off[b] + atomicAdd(&g_cur[b], 1); g_adj[pb] = a;
}

// ---------------- layer-0 per-node GEMM, fused neighbor gather -----------------
// smem: ws0s[9472] wn0s[9472] xs[4736] as[4736] = 28416 floats
__global__ void __launch_bounds__(256) k_pernode2(const float* __restrict__ ws0,
                                                  const float* __restrict__ wn0,
                                                  const float* __restrict__ b0) {
    extern __shared__ float sm[];
    float* ws0s = sm;
    float* wn0s = sm + 9472;
    float* xs   = sm + 18944;
    float* as_  = sm + 23680;
    int t = threadIdx.x;
    int tile = blockIdx.x;                   // 157 tiles of 32 nodes
    for (int i = t; i < XND*HD; i += 256) { ws0s[i] = ws0[i]; wn0s[i] = wn0[i]; }
    // stage own xn rows + gather neighbor mean (148-dim) into smem
    for (int i = t; i < 32*37; i += 256) {
        int s = i / 37, q = i % 37;
        int node = tile*32 + s;
        float4 xv = make_float4(0,0,0,0);
        float4 acc = make_float4(0,0,0,0);
        if (node < NN) {
            xv = ((const float4*)g_xn)[node*37 + q];
            int s0 = g_off[node], e0 = g_off[node+1];
            float inv = 1.0f / fmaxf((float)(e0 - s0), 1.0f);
            for (int j = s0; j < e0; j++) {
                float4 v = ((const float4*)g_xn)[g_adj[j]*37 + q];
                acc.x += v.x; acc.y += v.y; acc.z += v.z; acc.w += v.w;
            }
            acc.x *= inv; acc.y *= inv; acc.z *= inv; acc.w *= inv;
        }
        ((float4*)xs)[i] = xv;
        ((float4*)as_)[i] = acc;
    }
    __syncthreads();

    int rg = t >> 4, cg = t & 15;
    float4 b4 = *(const float4*)(b0 + cg*4);
    ull acc[2][2];
    acc[0][0] = f2pack(b4.x, b4.y); acc[0][1] = f2pack(b4.z, b4.w);
    acc[1][0] = acc[0][0];          acc[1][1] = acc[0][1];

    for (int dc = 0; dc < XND; dc += 4) {
        float4 x0 = *(const float4*)(xs  + (rg*2+0)*XND + dc);
        float4 x1 = *(const float4*)(xs  + (rg*2+1)*XND + dc);
        float4 a0 = *(const float4*)(as_ + (rg*2+0)*XND + dc);
        float4 a1 = *(const float4*)(as_ + (rg*2+1)*XND + dc);
        #pragma unroll
        for (int i = 0; i < 4; i++) {
            const ull* w1p = (const ull*)(ws0s + (dc+i)*HD + cg*4);
            const ull* w2p = (const ull*)(wn0s + (dc+i)*HD + cg*4);
            ull w1lo = w1p[0], w1hi = w1p[1];
            ull w2lo = w2p[0], w2hi = w2p[1];
            {
                float hx = ((const float*)&x0)[i], ax = ((const float*)&a0)[i];
                ull hb = f2pack(hx,hx), ab = f2pack(ax,ax);
                acc[0][0] = fma2(hb, w1lo, acc[0][0]);
                acc[0][0] = fma2(ab, w2lo, acc[0][0]);
                acc[0][1] = fma2(hb, w1hi, acc[0][1]);
                acc[0][1] = fma2(ab, w2hi, acc[0][1]);
            }
            {
                float hx = ((const float*)&x1)[i], ax = ((const float*)&a1)[i];
                ull hb = f2pack(hx,hx), ab = f2pack(ax,ax);
                acc[1][0] = fma2(hb, w1lo, acc[1][0]);
                acc[1][0] = fma2(ab, w2lo, acc[1][0]);
                acc[1][1] = fma2(hb, w1hi, acc[1][1]);
                acc[1][1] = fma2(ab, w2hi, acc[1][1]);
            }
        }
    }
    #pragma unroll
    for (int n = 0; n < 2; n++) {
        int node = tile*32 + rg*2 + n;
        if (node < NN) {
            float2 lo = f2unpack(acc[n][0]), hi = f2unpack(acc[n][1]);
            ((float4*)(g_pernode + node*HD))[cg] = make_float4(lo.x, lo.y, hi.x, hi.y);
        }
    }
}

// =============== layer 1: on-the-fly h0 + dual GEMM + skip0-on-input ===========
// h0[j][c][:] = relu(pern[j] + t1[c]) for every gathered neighbor (deg[j]>=1).
// smem: sws[4096] swn[4096] ssp[4096] hsb[4096] asb[4096] t1s[2048] t0s[2048] b[128]
__global__ void __launch_bounds__(256, 2) k_layer_first(
        float* __restrict__ hnew,
        const float* __restrict__ wself, const float* __restrict__ wneigh,
        const float* __restrict__ bias,
        const float* __restrict__ skw0, const float* __restrict__ skb0) {
    extern __shared__ float sm[];
    float* sws = sm;
    float* swn = sm + 4096;
    float* ssp = sm + 8192;
    float* hsb = sm + 12288;
    float* asb = sm + 16384;
    float* t1s = sm + 20480;
    float* t0s = sm + 22528;
    float* bds = sm + 24576;
    float* bps = sm + 24640;
    int t = threadIdx.x;
    for (int i = t; i < HD*HD; i += 256) {
        sws[i] = wself[i]; swn[i] = wneigh[i]; ssp[i] = skw0[i];
    }
    for (int i = t; i < NC*HD; i += 256) { t1s[i] = g_t1[i]; t0s[i] = g_t0[i]; }
    if (t < HD) { bds[t] = bias[t]; bps[t] = skb0[t]; }
    __syncthreads();

    int half = t >> 7, wt = t & 127;
    int rg = wt >> 4, kq = wt & 15;
    float* hsn = hsb + half*2048;
    float* asn = asb + half*2048;
    // hoist this thread's 4 t1 slices (c = rg + 8m, col group kq)
    float4 t1r[4];
    #pragma unroll
    for (int m = 0; m < 4; m++) t1r[m] = ((const float4*)t1s)[(rg + 8*m)*16 + kq];

    ull bdlo = f2pack(bds[kq*4], bds[kq*4+1]), bdhi = f2pack(bds[kq*4+2], bds[kq*4+3]);
    ull bplo = f2pack(bps[kq*4], bps[kq*4+1]), bphi = f2pack(bps[kq*4+2], bps[kq*4+3]);
    float poolp[4][4];
    #pragma unroll
    for (int r = 0; r < 4; r++)
        #pragma unroll
        for (int c = 0; c < 4; c++) poolp[r][c] = 0.0f;

    for (int base = blockIdx.x*2; base < NN; base += gridDim.x*2) {
        int node = base + half;
        __syncthreads();
        int s0 = g_off[node], e0 = g_off[node+1];
        float inv = 1.0f / fmaxf((float)(e0 - s0), 1.0f);
        float4 pown = ((const float4*)g_pernode)[node*16 + kq];
        // own h0 row (deg==0 -> t0)
        if (e0 > s0) {
            #pragma unroll
            for (int m = 0; m < 4; m++) {
                float4 r = relu4(make_float4(pown.x + t1r[m].x, pown.y + t1r[m].y,
                                             pown.z + t1r[m].z, pown.w + t1r[m].w));
                ((float4*)hsn)[wt + 128*m] = r;
            }
        } else {
            #pragma unroll
            for (int m = 0; m < 4; m++) {
                float4 t0v = ((const float4*)t0s)[(rg + 8*m)*16 + kq];
                float4 r = relu4(make_float4(pown.x + t0v.x, pown.y + t0v.y,
                                             pown.z + t0v.z, pown.w + t0v.w));
                ((float4*)hsn)[wt + 128*m] = r;
            }
        }
        // gather: agg[c] = mean_j relu(pern[j] + t1[c])
        float4 ga[4];
        #pragma unroll
        for (int m = 0; m < 4; m++) ga[m] = make_float4(0,0,0,0);
        for (int j = s0; j < e0; j++) {
            float4 p = ((const float4*)g_pernode)[g_adj[j]*16 + kq];
            #pragma unroll
            for (int m = 0; m < 4; m++) {
                ga[m].x += fmaxf(p.x + t1r[m].x, 0.f);
                ga[m].y += fmaxf(p.y + t1r[m].y, 0.f);
                ga[m].z += fmaxf(p.z + t1r[m].z, 0.f);
                ga[m].w += fmaxf(p.w + t1r[m].w, 0.f);
            }
        }
        #pragma unroll
        for (int m = 0; m < 4; m++) {
            ga[m].x *= inv; ga[m].y *= inv; ga[m].z *= inv; ga[m].w *= inv;
            ((float4*)asn)[wt + 128*m] = ga[m];
        }
        __syncthreads();

        // triple GEMM (dual + skip-on-input), rows rg*4..+3, cols kq*4..+3
        ull accd[4][2], acck[4][2];
        #pragma unroll
        for (int r = 0; r < 4; r++) {
            accd[r][0] = bdlo; accd[r][1] = bdhi;
            acck[r][0] = bplo; acck[r][1] = bphi;
        }
        for (int dc = 0; dc < HD; dc += 4) {
            float4 h[4], a[4];
            #pragma unroll
            for (int r = 0; r < 4; r++) {
                h[r] = *(const float4*)(hsn + (rg*4+r)*HD + dc);
                a[r] = *(const float4*)(asn + (rg*4+r)*HD + dc);
            }
            #pragma unroll
            for (int i = 0; i < 4; i++) {
                const ull* w1p = (const ull*)(sws + (dc+i)*HD + kq*4);
                const ull* w2p = (const ull*)(swn + (dc+i)*HD + kq*4);
                const ull* wkp = (const ull*)(ssp + (dc+i)*HD + kq*4);
                ull w1lo = w1p[0], w1hi = w1p[1];
                ull w2lo = w2p[0], w2hi = w2p[1];
                ull wklo = wkp[0], wkhi = wkp[1];
                #pragma unroll
                for (int r = 0; r < 4; r++) {
                    float hx = ((const float*)&h[r])[i];
                    float ax = ((const float*)&a[r])[i];
                    ull hb = f2pack(hx, hx);
                    ull ab = f2pack(ax, ax);
                    accd[r][0] = fma2(hb, w1lo, accd[r][0]);
                    accd[r][0] = fma2(ab, w2lo, accd[r][0]);
                    accd[r][1] = fma2(hb, w1hi, accd[r][1]);
                    accd[r][1] = fma2(ab, w2hi, accd[r][1]);
                    acck[r][0] = fma2(hb, wklo, acck[r][0]);
                    acck[r][1] = fma2(hb, wkhi, acck[r][1]);
                }
            }
        }
        #pragma unroll
        for (int r = 0; r < 4; r++) {
            float2 lo = f2unpack(accd[r][0]), hi = f2unpack(accd[r][1]);
            *(float4*)(hnew + (size_t)node*ROWLEN + (rg*4+r)*HD + kq*4) =
                make_float4(fmaxf(lo.x,0.f), fmaxf(lo.y,0.f),
                            fmaxf(hi.x,0.f), fmaxf(hi.y,0.f));
            float2 klo = f2unpack(acck[r][0]), khi = f2unpack(acck[r][1]);
            poolp[r][0] += fmaxf(klo.x, 0.f); poolp[r][1] += fmaxf(klo.y, 0.f);
            poolp[r][2] += fmaxf(khi.x, 0.f); poolp[r][3] += fmaxf(khi.y, 0.f);
        }
    }
    __syncthreads();
    if (half == 1) {
        #pragma unroll
        for (int r = 0; r < 4; r++)
            #pragma unroll
            for (int c = 0; c < 4; c++) hsb[wt*16 + r*4 + c] = poolp[r][c];
    }
    __syncthreads();
    if (half == 0) {
        #pragma unroll
        for (int r = 0; r < 4; r++)
            #pragma unroll
            for (int c = 0; c < 4; c++) {
                float v = poolp[r][c] + hsb[wt*16 + r*4 + c];
                atomicAdd(&g_pool[(rg*4+r)*POOLD + 0*HD + kq*4 + c], v);
            }
    }
}

// =============== layer 2 (last): gather h1 + dual GEMM + skip1-in + skip2-out ==
// No h2 store: h2 is consumed entirely by skip2 in-kernel.
__global__ void __launch_bounds__(256, 2) k_layer_last(
        const float* __restrict__ hold,
        const float* __restrict__ wself, const float* __restrict__ wneigh,
        const float* __restrict__ bias,
        const float* __restrict__ skwp, const float* __restrict__ skbp,
        const float* __restrict__ skwo, const float* __restrict__ skbo) {
    extern __shared__ float sm[];
    float* sws = sm;
    float* swn = sm + 4096;
    float* ssp = sm + 8192;
    float* sso = sm + 12288;
    float* hsb = sm + 16384;
    float* asb = sm + 20480;
    float* bds = sm + 24576;
    float* bps = sm + 24640;
    float* bos = sm + 24704;
    int t = threadIdx.x;
    for (int i = t; i < HD*HD; i += 256) {
        sws[i] = wself[i]; swn[i] = wneigh[i]; ssp[i] = skwp[i]; sso[i] = skwo[i];
    }
    if (t < HD) { bds[t] = bias[t]; bps[t] = skbp[t]; bos[t] = skbo[t]; }
    __syncthreads();

    int half = t >> 7, wt = t & 127;
    int rg = wt >> 4, kq = wt & 15;
    float* hsn = hsb + half*2048;
    float* asn = asb + half*2048;
    ull bdlo = f2pack(bds[kq*4], bds[kq*4+1]), bdhi = f2pack(bds[kq*4+2], bds[kq*4+3]);
    ull bplo = f2pack(bps[kq*4], bps[kq*4+1]), bphi = f2pack(bps[kq*4+2], bps[kq*4+3]);
    ull bolo = f2pack(bos[kq*4], bos[kq*4+1]), bohi = f2pack(bos[kq*4+2], bos[kq*4+3]);
    float poolp[4][4], poolo[4][4];
    #pragma unroll
    for (int r = 0; r < 4; r++)
        #pragma unroll
        for (int c = 0; c < 4; c++) { poolp[r][c] = 0.0f; poolo[r][c] = 0.0f; }

    for (int base = blockIdx.x*2; base < NN; base += gridDim.x*2) {
        int node = base + half;
        __syncthreads();
        int s0 = g_off[node], e0 = g_off[node+1];
        float inv = 1.0f / fmaxf((float)(e0 - s0), 1.0f);
        const float4* own = (const float4*)(hold + (size_t)node*ROWLEN);
        float4* h4 = (float4*)hsn;
        float4* a4 = (float4*)asn;
        h4[wt]     = own[wt];
        h4[wt+128] = own[wt+128];
        h4[wt+256] = own[wt+256];
        h4[wt+384] = own[wt+384];
        float4 ac0 = make_float4(0,0,0,0), ac1 = ac0, ac2 = ac0, ac3 = ac0;
        for (int j = s0; j < e0; j++) {
            const float4* row = (const float4*)(hold + (size_t)g_adj[j]*ROWLEN);
            float4 v0 = row[wt], v1 = row[wt+128], v2 = row[wt+256], v3 = row[wt+384];
            ac0.x += v0.x; ac0.y += v0.y; ac0.z += v0.z; ac0.w += v0.w;
            ac1.x += v1.x; ac1.y += v1.y; ac1.z += v1.z; ac1.w += v1.w;
            ac2.x += v2.x; ac2.y += v2.y; ac2.z += v2.z; ac2.w += v2.w;
            ac3.x += v3.x; ac3.y += v3.y; ac3.z += v3.z; ac3.w += v3.w;
        }
        ac0.x*=inv; ac0.y*=inv; ac0.z*=inv; ac0.w*=inv;
        ac1.x*=inv; ac1.y*=inv; ac1.z*=inv; ac1.w*=inv;
        ac2.x*=inv; ac2.y*=inv; ac2.z*=inv; ac2.w*=inv;
        ac3.x*=inv; ac3.y*=inv; ac3.z*=inv; ac3.w*=inv;
        a4[wt] = ac0; a4[wt+128] = ac1; a4[wt+256] = ac2; a4[wt+384] = ac3;
        __syncthreads();

        ull accd[4][2], acck[4][2];
        #pragma unroll
        for (int r = 0; r < 4; r++) {
            accd[r][0] = bdlo; accd[r][1] = bdhi;
            acck[r][0] = bplo; acck[r][1] = bphi;
        }
        for (int dc = 0; dc < HD; dc += 4) {
            float4 h[4], a[4];
            #pragma unroll
            for (int r = 0; r < 4; r++) {
                h[r] = *(const float4*)(hsn + (rg*4+r)*HD + dc);
                a[r] = *(const float4*)(asn + (rg*4+r)*HD + dc);
            }
            #pragma unroll
            for (int i = 0; i < 4; i++) {
                const ull* w1p = (const ull*)(sws + (dc+i)*HD + kq*4);
                const ull* w2p = (const ull*)(swn + (dc+i)*HD + kq*4);
                const ull* wkp = (const ull*)(ssp + (dc+i)*HD + kq*4);
                ull w1lo = w1p[0], w1hi = w1p[1];
                ull w2lo = w2p[0], w2hi = w2p[1];
                ull wklo = wkp[0], wkhi = wkp[1];
                #pragma unroll
                for (int r = 0; r < 4; r++) {
                    float hx = ((const float*)&h[r])[i];
                    float ax = ((const float*)&a[r])[i];
                    ull hb = f2pack(hx, hx);
                    ull ab = f2pack(ax, ax);
                    accd[r][0] = fma2(hb, w1lo, accd[r][0]);
                    accd[r][0] = fma2(ab, w2lo, accd[r][0]);
                    accd[r][1] = fma2(hb, w1hi, accd[r][1]);
                    accd[r][1] = fma2(ab, w2hi, accd[r][1]);
                    acck[r][0] = fma2(hb, wklo, acck[r][0]);
                    acck[r][1] = fma2(hb, wkhi, acck[r][1]);
                }
            }
        }
        float4 rr[4];
        #pragma unroll
        for (int r = 0; r < 4; r++) {
            float2 lo = f2unpack(accd[r][0]), hi = f2unpack(accd[r][1]);
            rr[r] = make_float4(fmaxf(lo.x,0.f), fmaxf(lo.y,0.f),
                                fmaxf(hi.x,0.f), fmaxf(hi.y,0.f));
            float2 klo = f2unpack(acck[r][0]), khi = f2unpack(acck[r][1]);
            poolp[r][0] += fmaxf(klo.x, 0.f); poolp[r][1] += fmaxf(klo.y, 0.f);
            poolp[r][2] += fmaxf(khi.x, 0.f); poolp[r][3] += fmaxf(khi.y, 0.f);
        }
        __syncthreads();
        #pragma unroll
        for (int r = 0; r < 4; r++)
            *(float4*)(hsn + (rg*4+r)*HD + kq*4) = rr[r];
        __syncthreads();
        ull acco[4][2];
        #pragma unroll
        for (int r = 0; r < 4; r++) { acco[r][0] = bolo; acco[r][1] = bohi; }
        for (int dc = 0; dc < HD; dc += 4) {
            float4 h[4];
            #pragma unroll
            for (int r = 0; r < 4; r++)
                h[r] = *(const float4*)(hsn + (rg*4+r)*HD + dc);
            #pragma unroll
            for (int i = 0; i < 4; i++) {
                const ull* wp = (const ull*)(sso + (dc+i)*HD + kq*4);
                ull wlo = wp[0], whi = wp[1];
                #pragma unroll
                for (int r = 0; r < 4; r++) {
                    float hx = ((const float*)&h[r])[i];
                    ull hb = f2pack(hx, hx);
                    acco[r][0] = fma2(hb, wlo, acco[r][0]);
                    acco[r][1] = fma2(hb, whi, acco[r][1]);
                }
            }
        }
        #pragma unroll
        for (int r = 0; r < 4; r++) {
            float2 lo = f2unpack(acco[r][0]), hi = f2unpack(acco[r][1]);
            poolo[r][0] += fmaxf(lo.x, 0.f); poolo[r][1] += fmaxf(lo.y, 0.f);
            poolo[r][2] += fmaxf(hi.x, 0.f); poolo[r][3] += fmaxf(hi.y, 0.f);
        }
    }
    __syncthreads();
    if (half == 1) {
        #pragma unroll
        for (int r = 0; r < 4; r++)
            #pragma unroll
            for (int c = 0; c < 4; c++) {
                hsb[wt*16 + r*4 + c] = poolp[r][c];
                asb[wt*16 + r*4 + c] = poolo[r][c];
            }
    }
    __syncthreads();
    if (half == 0) {
        #pragma unroll
        for (int r = 0; r < 4; r++)
            #pragma unroll
            for (int c = 0; c < 4; c++) {
                float v = poolp[r][c] + hsb[wt*16 + r*4 + c];
                atomicAdd(&g_pool[(rg*4+r)*POOLD + 1*HD + kq*4 + c], v);
                float w = poolo[r][c] + asb[wt*16 + r*4 + c];
                atomicAdd(&g_pool[(rg*4+r)*POOLD + 2*HD + kq*4 + c], w);
            }
    }
}

// ---------------- final MLP ----------------------------------------------------
__global__ void k_mlp(const float* __restrict__ p1w, const float* __restrict__ p1b,
                      const float* __restrict__ p2w, const float* __restrict__ p2b,
                      const float* __restrict__ p3w, const float* __restrict__ p3b,
                      float* __restrict__ out) {
    int c = blockIdx.x;
    int t = threadIdx.x;  // 128
    __shared__ float pr[POOLD], y1[128], y2[64];
    for (int i = t; i < POOLD; i += 128) pr[i] = g_pool[c*POOLD + i];
    __syncthreads();
    float s = p1b[t];
    #pragma unroll 4
    for (int d = 0; d < POOLD; d++) s += pr[d] * p1w[d*128 + t];
    y1[t] = fmaxf(s, 0.f);
    __syncthreads();
    if (t < 64) {
        float s2 = p2b[t];
        #pragma unroll 4
        for (int d = 0; d < 128; d++) s2 += y1[d] * p2w[d*64 + t];
        y2[t] = fmaxf(s2, 0.f);
    }
    __syncthreads();
    if (t == 0) {
        float s3 = p3b[0];
        for (int d = 0; d < 64; d++) s3 += y2[d] * p3w[d];
        out[c] = s3;
    }
}

// ---------------- launch -------------------------------------------------------
extern "C" void kernel_launch(void* const* d_in, const int* in_sizes, int n_in,
                              void* d_out, int out_size) {
    const float* nf     = (const float*)d_in[0];
    const void*  opc    = d_in[1];
    const void*  ei     = d_in[2];
    const float* cf     = (const float*)d_in[3];
    const float* op_emb = (const float*)d_in[4];
    const float* ws0    = (const float*)d_in[5];
    const float* wn0    = (const float*)d_in[6];
    const float* b0     = (const float*)d_in[7];
    const float* ws     = (const float*)d_in[8];
    const float* wnn    = (const float*)d_in[9];
    const float* bb     = (const float*)d_in[10];
    const float* skw    = (const float*)d_in[11];
    const float* skb    = (const float*)d_in[12];
    const float* p1w    = (const float*)d_in[13];
    const float* p1b    = (const float*)d_in[14];
    const float* p2w    = (const float*)d_in[15];
    const float* p2b    = (const float*)d_in[16];
    const float* p3w    = (const float*)d_in[17];
    const float* p3b    = (const float*)d_in[18];
    float* out = (float*)d_out;

    const int SMEM_LF = 24704 * (int)sizeof(float);  // 98816 B
    const int SMEM_LL = 24768 * (int)sizeof(float);  // 99072 B
    const int SMEM_PN = 28416 * (int)sizeof(float);  // 113664 B
    cudaFuncSetAttribute(k_layer_first,
                         cudaFuncAttributeMaxDynamicSharedMemorySize, SMEM_LF);
    cudaFuncSetAttribute(k_layer_last,
                         cudaFuncAttributeMaxDynamicSharedMemorySize, SMEM_LL);
    cudaFuncSetAttribute(k_pernode2,
                         cudaFuncAttributeMaxDynamicSharedMemorySize, SMEM_PN);

    float* ph1 = nullptr;
    cudaGetSymbolAddress((void**)&ph1, g_h1);

    k_pre<<<32, 256>>>(opc, ei);
    k_xn_deg<<<(NN*XND + 255)/256, 256>>>(nf, opc, op_emb, ei);
    k_scan_cfg<<<3, 1024>>>(cf, ws0, wn0);
    k_fill<<<(NE + 255)/256, 256>>>(ei);
    k_pernode2<<<157, 256, SMEM_PN>>>(ws0, wn0, b0);
    k_layer_first<<<296, 256, SMEM_LF>>>(ph1, ws, wnn, bb, skw, skb);
    k_layer_last<<<296, 256, SMEM_LL>>>(ph1, ws + HD*HD, wnn + HD*HD, bb + HD,
                                        skw + HD*HD, skb + HD,
                                        skw + 2*HD*HD, skb + 2*HD);
    k_mlp<<<32, 128>>>(p1w, p1b, p2w, p2b, p3w, p3b, out);
}

// round 6
// speedup vs baseline: 4.5673x; 1.6226x over previous
#include <cuda_runtime.h>

#define NN   5000
#define NE   8000
#define NDIR (2*NE)
#define NC   32
#define HD   64
#define NF   140
#define OPD  8
#define XND  148
#define CFD  24
#define POOLD 192
#define ROWLEN (NC*HD)   // 2048
#define STR  68          // padded smem row stride (conflict-free A-frag loads)

typedef unsigned long long ull;

__device__ __forceinline__ ull f2pack(float x, float y) {
    ull r; asm("mov.b64 %0,{%1,%2};" : "=l"(r) : "f"(x), "f"(y)); return r;
}
__device__ __forceinline__ ull fma2(ull a, ull b, ull c) {
    ull d; asm("fma.rn.f32x2 %0,%1,%2,%3;" : "=l"(d) : "l"(a), "l"(b), "l"(c)); return d;
}
__device__ __forceinline__ float2 f2unpack(ull v) {
    float lo, hi; asm("mov.b64 {%0,%1},%2;" : "=f"(lo), "=f"(hi) : "l"(v));
    float2 r; r.x = lo; r.y = hi; return r;
}
__device__ __forceinline__ float4 relu4(float4 a) {
    return make_float4(fmaxf(a.x,0.f), fmaxf(a.y,0.f), fmaxf(a.z,0.f), fmaxf(a.w,0.f));
}
__device__ __forceinline__ unsigned tf32cvt(float x) {
    unsigned r; asm("cvt.rna.tf32.f32 %0,%1;" : "=r"(r) : "f"(x)); return r;
}
__device__ __forceinline__ void mma_tf32(float* d, const unsigned* a,
                                         unsigned b0, unsigned b1) {
    asm volatile(
        "mma.sync.aligned.m16n8k8.row.col.f32.tf32.tf32.f32 "
        "{%0,%1,%2,%3},{%4,%5,%6,%7},{%8,%9},{%0,%1,%2,%3};"
        : "+f"(d[0]), "+f"(d[1]), "+f"(d[2]), "+f"(d[3])
        : "r"(a[0]), "r"(a[1]), "r"(a[2]), "r"(a[3]), "r"(b0), "r"(b1));
}

// ---------------- device scratch ---------------------------------------------
__device__ __align__(16) float g_xn[NN*XND];
__device__ __align__(16) float g_pernode[NN*HD];
__device__ __align__(16) float g_t1[NC*HD];
__device__ __align__(16) float g_t0[NC*HD];
__device__ __align__(16) float g_h1[(size_t)NN*ROWLEN];
__device__ int   g_deg[NN];
__device__ int   g_off[NN+1];
__device__ int   g_cur[NN];
__device__ int   g_adj[NDIR];
__device__ float g_pool[NC*POOLD];
__device__ int g_op64 = 1, g_ed64 = 1;  // monotone, input-determined

__device__ __forceinline__ int idx_at(const void* p, int i, int is64) {
    if (is64) return (int)((const long long*)p)[i];
    return ((const int*)p)[i];
}

// pre-swizzle a 64x64 row-major weight matrix into mma B-fragment order (tf32).
// frag index: ((ntile*8 + kstep)*32 + lane)*2 + j ; value W[kstep*8+tg+j*4][ntile*8+g]
__device__ __forceinline__ void load_frags(float* dst, const float* __restrict__ W, int t) {
    for (int i = t; i < 4096; i += 256) {
        int j = i & 1, lane = (i >> 1) & 31, ks = (i >> 6) & 7, nt = (i >> 9) & 7;
        int g = lane >> 2, tg = lane & 3;
        ((unsigned*)dst)[i] = tf32cvt(W[(ks*8 + tg + j*4)*64 + nt*8 + g]);
    }
}

// ---------------- pre: zero state + dtype detection ---------------------------
__global__ void k_pre(const void* opc, const void* ei) {
    int i = blockIdx.x * blockDim.x + threadIdx.x;
    if (i < NC*POOLD) g_pool[i] = 0.0f;
    if (i < NN) { g_deg[i] = 0; g_cur[i] = 0; }
    if (i < 2500) { if (((const unsigned*)opc)[2*i+1] != 0u) g_op64 = 0; }
    if (i < 8000) { if (((const unsigned*)ei )[2*i+1] != 0u) g_ed64 = 0; }
}

// ---------------- xn assembly + degree count ----------------------------------
__global__ void k_xn_deg(const float* __restrict__ nf, const void* __restrict__ opc,
                         const float* __restrict__ op_emb, const void* __restrict__ ei) {
    int idx = blockIdx.x * blockDim.x + threadIdx.x;
    if (idx < NN*XND) {
        int n = idx / XND, d = idx % XND;
        if (d < NF) g_xn[idx] = nf[n*NF + d];
        else {
            int op = idx_at(opc, n, g_op64);
            g_xn[idx] = op_emb[op*OPD + (d - NF)];
        }
    }
    if (idx < NE) {
        int a = idx_at(ei, 2*idx,   g_ed64);
        int b = idx_at(ei, 2*idx+1, g_ed64);
        atomicAdd(&g_deg[a], 1);
        atomicAdd(&g_deg[b], 1);
    }
}

// ---------------- scan (block 0) + cfg terms (blocks 1,2) ---------------------
__global__ void k_scan_cfg(const float* __restrict__ cf, const float* __restrict__ ws0,
                           const float* __restrict__ wn0) {
    if (blockIdx.x == 0) {
        __shared__ int s[1024];
        int t = threadIdx.x;
        const int CH = 5;
        int base = t * CH;
        int v[CH]; int tot = 0;
        #pragma unroll
        for (int i = 0; i < CH; i++) {
            int idx = base + i;
            v[i] = (idx < NN) ? g_deg[idx] : 0;
            tot += v[i];
        }
        s[t] = tot; __syncthreads();
        for (int ofs = 1; ofs < 1024; ofs <<= 1) {
            int val = s[t];
            int add = (t >= ofs) ? s[t - ofs] : 0;
            __syncthreads();
            s[t] = val + add;
            __syncthreads();
        }
        int run = s[t] - tot;
        #pragma unroll
        for (int i = 0; i < CH; i++) {
            int idx = base + i;
            if (idx < NN) { g_off[idx] = run; run += v[i]; }
        }
        if (t == 1023) g_off[NN] = s[1023];
    } else {
        int idx = (blockIdx.x - 1) * 1024 + threadIdx.x;
        if (idx >= NC*HD) return;
        int c = idx >> 6, k = idx & 63;
        float s1 = 0.0f, s0v = 0.0f;
        #pragma unroll
        for (int d = 0; d < CFD; d++) {
            float cv = cf[c*CFD + d];
            float a  = ws0[(XND + d)*HD + k];
            float bq = wn0[(XND + d)*HD + k];
            s0v += cv * a;
            s1  += cv * (a + bq);
        }
        g_t0[idx] = s0v;
        g_t1[idx] = s1;
    }
}

__global__ void k_fill(const void* __restrict__ ei) {
    int t = blockIdx.x * blockDim.x + threadIdx.x;
    if (t >= NE) return;
    int a = idx_at(ei, 2*t,   g_ed64);
    int b = idx_at(ei, 2*t+1, g_ed64);
    int pa = g_off[a] + atomicAdd(&g_cur[a], 1); g_adj[pa] = b;
    int pb = g_off[b] + atomicAdd(&g_cur[b], 1); g_adj[pb] = a;
}

// ---------------- layer-0 per-node GEMM (SIMT f32x2; tiny) ---------------------
__global__ void __launch_bounds__(256) k_pernode2(const float* __restrict__ ws0,
                                                  const float* __restrict__ wn0,
                                                  const float* __restrict__ b0) {
    extern __shared__ float sm[];
    float* ws0s = sm;
    float* wn0s = sm + 9472;
    float* xs   = sm + 18944;
    float* as_  = sm + 23680;
    int t = threadIdx.x;
    int tile = blockIdx.x;
    for (int i = t; i < XND*HD; i += 256) { ws0s[i] = ws0[i]; wn0s[i] = wn0[i]; }
    for (int i = t; i < 32*37; i += 256) {
        int s = i / 37, q = i % 37;
        int node = tile*32 + s;
        float4 xv = make_float4(0,0,0,0);
        float4 acc = make_float4(0,0,0,0);
        if (node < NN) {
            xv = ((const float4*)g_xn)[node*37 + q];
            int s0 = g_off[node], e0 = g_off[node+1];
            float inv = 1.0f / fmaxf((float)(e0 - s0), 1.0f);
            for (int j = s0; j < e0; j++) {
                float4 v = ((const float4*)g_xn)[g_adj[j]*37 + q];
                acc.x += v.x; acc.y += v.y; acc.z += v.z; acc.w += v.w;
            }
            acc.x *= inv; acc.y *= inv; acc.z *= inv; acc.w *= inv;
        }
        ((float4*)xs)[i] = xv;
        ((float4*)as_)[i] = acc;
    }
    __syncthreads();

    int rg = t >> 4, cg = t & 15;
    float4 b4 = *(const float4*)(b0 + cg*4);
    ull acc[2][2];
    acc[0][0] = f2pack(b4.x, b4.y); acc[0][1] = f2pack(b4.z, b4.w);
    acc[1][0] = acc[0][0];          acc[1][1] = acc[0][1];

    for (int dc = 0; dc < XND; dc += 4) {
        float4 x0 = *(const float4*)(xs  + (rg*2+0)*XND + dc);
        float4 x1 = *(const float4*)(xs  + (rg*2+1)*XND + dc);
        float4 a0 = *(const float4*)(as_ + (rg*2+0)*XND + dc);
        float4 a1 = *(const float4*)(as_ + (rg*2+1)*XND + dc);
        #pragma unroll
        for (int i = 0; i < 4; i++) {
            const ull* w1p = (const ull*)(ws0s + (dc+i)*HD + cg*4);
            const ull* w2p = (const ull*)(wn0s + (dc+i)*HD + cg*4);
            ull w1lo = w1p[0], w1hi = w1p[1];
            ull w2lo = w2p[0], w2hi = w2p[1];
            {
                float hx = ((const float*)&x0)[i], ax = ((const float*)&a0)[i];
                ull hb = f2pack(hx,hx), ab = f2pack(ax,ax);
                acc[0][0] = fma2(hb, w1lo, acc[0][0]);
                acc[0][0] = fma2(ab, w2lo, acc[0][0]);
                acc[0][1] = fma2(hb, w1hi, acc[0][1]);
                acc[0][1] = fma2(ab, w2hi, acc[0][1]);
            }
            {
                float hx = ((const float*)&x1)[i], ax = ((const float*)&a1)[i];
                ull hb = f2pack(hx,hx), ab = f2pack(ax,ax);
                acc[1][0] = fma2(hb, w1lo, acc[1][0]);
                acc[1][0] = fma2(ab, w2lo, acc[1][0]);
                acc[1][1] = fma2(hb, w1hi, acc[1][1]);
                acc[1][1] = fma2(ab, w2hi, acc[1][1]);
            }
        }
    }
    #pragma unroll
    for (int n = 0; n < 2; n++) {
        int node = tile*32 + rg*2 + n;
        if (node < NN) {
            float2 lo = f2unpack(acc[n][0]), hi = f2unpack(acc[n][1]);
            ((float4*)(g_pernode + node*HD))[cg] = make_float4(lo.x, lo.y, hi.x, hi.y);
        }
    }
}

// =============== layer 1 (tensor core): on-the-fly h0 + dual + skip0 ==========
// smem floats: wsF[4096] wnF[4096] spF[4096] hs[2x2176] as[2x2176] t1s[2048] t0s[2048] b[128]
__global__ void __launch_bounds__(256) k_layer_first(
        float* __restrict__ hnew,
        const float* __restrict__ wself, const float* __restrict__ wneigh,
        const float* __restrict__ bias,
        const float* __restrict__ skw0, const float* __restrict__ skb0) {
    extern __shared__ float sm[];
    float* wsF = sm;
    float* wnF = sm + 4096;
    float* spF = sm + 8192;
    float* hsb = sm + 12288;   // 2 x 2176
    float* asb = sm + 16640;   // 2 x 2176
    float* t1s = sm + 20992;
    float* t0s = sm + 23040;
    float* bds = sm + 25088;
    float* bps = sm + 25152;
    int t = threadIdx.x;
    load_frags(wsF, wself, t);
    load_frags(wnF, wneigh, t);
    load_frags(spF, skw0, t);
    for (int i = t; i < NC*HD; i += 256) { t1s[i] = g_t1[i]; t0s[i] = g_t0[i]; }
    if (t < HD) { bds[t] = bias[t]; bps[t] = skb0[t]; }
    __syncthreads();

    int half = t >> 7, wt = t & 127;
    int lane = t & 31, w = wt >> 5;
    int g = lane >> 2, tg = lane & 3;
    int rg = wt >> 4, kq = wt & 15;
    float* hs = hsb + half*2176;
    float* as = asb + half*2176;
    float4 t1r[4];
    #pragma unroll
    for (int m = 0; m < 4; m++) t1r[m] = ((const float4*)t1s)[(rg + 8*m)*16 + kq];

    float poolp[2][2][4];
    #pragma unroll
    for (int mt = 0; mt < 2; mt++)
        #pragma unroll
        for (int nt = 0; nt < 2; nt++)
            #pragma unroll
            for (int e = 0; e < 4; e++) poolp[mt][nt][e] = 0.0f;

    for (int base = blockIdx.x*2; base < NN; base += gridDim.x*2) {
        int node = base + half;
        __syncthreads();
        int s0 = g_off[node], e0 = g_off[node+1];
        float inv = 1.0f / fmaxf((float)(e0 - s0), 1.0f);
        float4 pown = ((const float4*)g_pernode)[node*16 + kq];
        // own h0 rows + neighbor-mean agg rows into strided smem
        #pragma unroll
        for (int m = 0; m < 4; m++) {
            int c = rg + 8*m;
            float4 tsel = t1r[m];
            if (e0 == s0) tsel = ((const float4*)t0s)[c*16 + kq];
            float4 r = relu4(make_float4(pown.x + tsel.x, pown.y + tsel.y,
                                         pown.z + tsel.z, pown.w + tsel.w));
            *(float4*)(hs + c*STR + kq*4) = r;
        }
        float4 ga[4];
        #pragma unroll
        for (int m = 0; m < 4; m++) ga[m] = make_float4(0,0,0,0);
        for (int j = s0; j < e0; j++) {
            float4 p = ((const float4*)g_pernode)[g_adj[j]*16 + kq];
            #pragma unroll
            for (int m = 0; m < 4; m++) {
                ga[m].x += fmaxf(p.x + t1r[m].x, 0.f);
                ga[m].y += fmaxf(p.y + t1r[m].y, 0.f);
                ga[m].z += fmaxf(p.z + t1r[m].z, 0.f);
                ga[m].w += fmaxf(p.w + t1r[m].w, 0.f);
            }
        }
        #pragma unroll
        for (int m = 0; m < 4; m++) {
            int c = rg + 8*m;
            ga[m].x *= inv; ga[m].y *= inv; ga[m].z *= inv; ga[m].w *= inv;
            *(float4*)(as + c*STR + kq*4) = ga[m];
        }
        __syncthreads();

        // mma: dual GEMM + skip0-on-input
        float accd[2][2][4], acck[2][2][4];
        #pragma unroll
        for (int mt = 0; mt < 2; mt++)
            #pragma unroll
            for (int nt = 0; nt < 2; nt++)
                #pragma unroll
                for (int e = 0; e < 4; e++) { accd[mt][nt][e] = 0.f; acck[mt][nt][e] = 0.f; }
        #pragma unroll
        for (int ks = 0; ks < 8; ks++) {
            int k0 = ks*8;
            unsigned ah[2][4], aa[2][4];
            #pragma unroll
            for (int mt = 0; mt < 2; mt++) {
                int r0 = mt*16 + g;
                ah[mt][0] = tf32cvt(hs[(r0  )*STR + k0 + tg]);
                ah[mt][1] = tf32cvt(hs[(r0+8)*STR + k0 + tg]);
                ah[mt][2] = tf32cvt(hs[(r0  )*STR + k0 + tg + 4]);
                ah[mt][3] = tf32cvt(hs[(r0+8)*STR + k0 + tg + 4]);
                aa[mt][0] = tf32cvt(as[(r0  )*STR + k0 + tg]);
                aa[mt][1] = tf32cvt(as[(r0+8)*STR + k0 + tg]);
                aa[mt][2] = tf32cvt(as[(r0  )*STR + k0 + tg + 4]);
                aa[mt][3] = tf32cvt(as[(r0+8)*STR + k0 + tg + 4]);
            }
            #pragma unroll
            for (int nt = 0; nt < 2; nt++) {
                int fi = (((w*2 + nt)*8 + ks)*32 + lane)*2;
                uint2 bs = *(const uint2*)((const unsigned*)wsF + fi);
                uint2 bn = *(const uint2*)((const unsigned*)wnF + fi);
                uint2 bp = *(const uint2*)((const unsigned*)spF + fi);
                #pragma unroll
                for (int mt = 0; mt < 2; mt++) {
                    mma_tf32(accd[mt][nt], ah[mt], bs.x, bs.y);
                    mma_tf32(accd[mt][nt], aa[mt], bn.x, bn.y);
                    mma_tf32(acck[mt][nt], ah[mt], bp.x, bp.y);
                }
            }
        }
        // epilogue: bias+relu -> h1 gmem; skip -> pool regs
        #pragma unroll
        for (int mt = 0; mt < 2; mt++)
            #pragma unroll
            for (int nt = 0; nt < 2; nt++) {
                int col = w*16 + nt*8 + 2*tg;
                float b0v = bds[col], b1v = bds[col+1];
                int r0 = mt*16 + g;
                float2 v0 = make_float2(fmaxf(accd[mt][nt][0] + b0v, 0.f),
                                        fmaxf(accd[mt][nt][1] + b1v, 0.f));
                float2 v1 = make_float2(fmaxf(accd[mt][nt][2] + b0v, 0.f),
                                        fmaxf(accd[mt][nt][3] + b1v, 0.f));
                *(float2*)(hnew + (size_t)node*ROWLEN + r0*HD + col) = v0;
                *(float2*)(hnew + (size_t)node*ROWLEN + (r0+8)*HD + col) = v1;
                float p0 = bps[col], p1 = bps[col+1];
                poolp[mt][nt][0] += fmaxf(acck[mt][nt][0] + p0, 0.f);
                poolp[mt][nt][1] += fmaxf(acck[mt][nt][1] + p1, 0.f);
                poolp[mt][nt][2] += fmaxf(acck[mt][nt][2] + p0, 0.f);
                poolp[mt][nt][3] += fmaxf(acck[mt][nt][3] + p1, 0.f);
            }
    }
    // pool merge across halves, then atomics (layer 0 slot)
    __syncthreads();
    if (half == 1) {
        #pragma unroll
        for (int mt = 0; mt < 2; mt++)
            #pragma unroll
            for (int nt = 0; nt < 2; nt++)
                #pragma unroll
                for (int e = 0; e < 4; e++)
                    wsF[wt*16 + (mt*2+nt)*4 + e] = poolp[mt][nt][e];
    }
    __syncthreads();
    if (half == 0) {
        #pragma unroll
        for (int mt = 0; mt < 2; mt++)
            #pragma unroll
            for (int nt = 0; nt < 2; nt++) {
                int col = w*16 + nt*8 + 2*tg;
                #pragma unroll
                for (int e = 0; e < 4; e++) {
                    float v = poolp[mt][nt][e] + wsF[wt*16 + (mt*2+nt)*4 + e];
                    int c = mt*16 + g + ((e >= 2) ? 8 : 0);
                    int cc = col + (e & 1);
                    atomicAdd(&g_pool[c*POOLD + 0*HD + cc], v);
                }
            }
    }
}

// =============== layer 2 (tensor core): gather + dual + skip1-in + skip2-out ===
// smem floats: wsF wnF spF soF [4x4096] hs[2x2176] as[2x2176] b[192]
__global__ void __launch_bounds__(256) k_layer_last(
        const float* __restrict__ hold,
        const float* __restrict__ wself, const float* __restrict__ wneigh,
        const float* __restrict__ bias,
        const float* __restrict__ skwp, const float* __restrict__ skbp,
        const float* __restrict__ skwo, const float* __restrict__ skbo) {
    extern __shared__ float sm[];
    float* wsF = sm;
    float* wnF = sm + 4096;
    float* spF = sm + 8192;
    float* soF = sm + 12288;
    float* hsb = sm + 16384;   // 2 x 2176
    float* asb = sm + 20736;   // 2 x 2176
    float* bds = sm + 25088;
    float* bps = sm + 25152;
    float* bos = sm + 25216;
    int t = threadIdx.x;
    load_frags(wsF, wself, t);
    load_frags(wnF, wneigh, t);
    load_frags(spF, skwp, t);
    load_frags(soF, skwo, t);
    if (t < HD) { bds[t] = bias[t]; bps[t] = skbp[t]; bos[t] = skbo[t]; }
    __syncthreads();

    int half = t >> 7, wt = t & 127;
    int lane = t & 31, w = wt >> 5;
    int g = lane >> 2, tg = lane & 3;
    int rg = wt >> 4, kq = wt & 15;
    float* hs = hsb + half*2176;
    float* as = asb + half*2176;

    float poolp[2][2][4], poolo[2][2][4];
    #pragma unroll
    for (int mt = 0; mt < 2; mt++)
        #pragma unroll
        for (int nt = 0; nt < 2; nt++)
            #pragma unroll
            for (int e = 0; e < 4; e++) { poolp[mt][nt][e] = 0.f; poolo[mt][nt][e] = 0.f; }

    for (int base = blockIdx.x*2; base < NN; base += gridDim.x*2) {
        int node = base + half;
        __syncthreads();
        int s0 = g_off[node], e0 = g_off[node+1];
        float inv = 1.0f / fmaxf((float)(e0 - s0), 1.0f);
        const float* own = hold + (size_t)node*ROWLEN;
        #pragma unroll
        for (int m = 0; m < 4; m++) {
            int c = rg + 8*m;
            *(float4*)(hs + c*STR + kq*4) = ((const float4*)own)[c*16 + kq];
        }
        float4 am[4];
        #pragma unroll
        for (int m = 0; m < 4; m++) am[m] = make_float4(0,0,0,0);
        for (int j = s0; j < e0; j++) {
            const float4* row = (const float4*)(hold + (size_t)g_adj[j]*ROWLEN);
            #pragma unroll
            for (int m = 0; m < 4; m++) {
                float4 v = row[(rg + 8*m)*16 + kq];
                am[m].x += v.x; am[m].y += v.y; am[m].z += v.z; am[m].w += v.w;
            }
        }
        #pragma unroll
        for (int m = 0; m < 4; m++) {
            int c = rg + 8*m;
            am[m].x *= inv; am[m].y *= inv; am[m].z *= inv; am[m].w *= inv;
            *(float4*)(as + c*STR + kq*4) = am[m];
        }
        __syncthreads();

        // mma: dual GEMM + skip1-on-input
        float accd[2][2][4], acck[2][2][4];
        #pragma unroll
        for (int mt = 0; mt < 2; mt++)
            #pragma unroll
            for (int nt = 0; nt < 2; nt++)
                #pragma unroll
                for (int e = 0; e < 4; e++) { accd[mt][nt][e] = 0.f; acck[mt][nt][e] = 0.f; }
        #pragma unroll
        for (int ks = 0; ks < 8; ks++) {
            int k0 = ks*8;
            unsigned ah[2][4], aa[2][4];
            #pragma unroll
            for (int mt = 0; mt < 2; mt++) {
                int r0 = mt*16 + g;
                ah[mt][0] = tf32cvt(hs[(r0  )*STR + k0 + tg]);
                ah[mt][1] = tf32cvt(hs[(r0+8)*STR + k0 + tg]);
                ah[mt][2] = tf32cvt(hs[(r0  )*STR + k0 + tg + 4]);
                ah[mt][3] = tf32cvt(hs[(r0+8)*STR + k0 + tg + 4]);
                aa[mt][0] = tf32cvt(as[(r0  )*STR + k0 + tg]);
                aa[mt][1] = tf32cvt(as[(r0+8)*STR + k0 + tg]);
                aa[mt][2] = tf32cvt(as[(r0  )*STR + k0 + tg + 4]);
                aa[mt][3] = tf32cvt(as[(r0+8)*STR + k0 + tg + 4]);
            }
            #pragma unroll
            for (int nt = 0; nt < 2; nt++) {
                int fi = (((w*2 + nt)*8 + ks)*32 + lane)*2;
                uint2 bs = *(const uint2*)((const unsigned*)wsF + fi);
                uint2 bn = *(const uint2*)((const unsigned*)wnF + fi);
                uint2 bp = *(const uint2*)((const unsigned*)spF + fi);
                #pragma unroll
                for (int mt = 0; mt < 2; mt++) {
                    mma_tf32(accd[mt][nt], ah[mt], bs.x, bs.y);
                    mma_tf32(accd[mt][nt], aa[mt], bn.x, bn.y);
                    mma_tf32(acck[mt][nt], ah[mt], bp.x, bp.y);
                }
            }
        }
        // skip1 pool; h2 = relu(dual+bias) staged back to hs for skip2
        __syncthreads();
        #pragma unroll
        for (int mt = 0; mt < 2; mt++)
            #pragma unroll
            for (int nt = 0; nt < 2; nt++) {
                int col = w*16 + nt*8 + 2*tg;
                float b0v = bds[col], b1v = bds[col+1];
                int r0 = mt*16 + g;
                *(float2*)(hs + r0*STR + col) =
                    make_float2(fmaxf(accd[mt][nt][0] + b0v, 0.f),
                                fmaxf(accd[mt][nt][1] + b1v, 0.f));
                *(float2*)(hs + (r0+8)*STR + col) =
                    make_float2(fmaxf(accd[mt][nt][2] + b0v, 0.f),
                                fmaxf(accd[mt][nt][3] + b1v, 0.f));
                float p0 = bps[col], p1 = bps[col+1];
                poolp[mt][nt][0] += fmaxf(acck[mt][nt][0] + p0, 0.f);
                poolp[mt][nt][1] += fmaxf(acck[mt][nt][1] + p1, 0.f);
                poolp[mt][nt][2] += fmaxf(acck[mt][nt][2] + p0, 0.f);
                poolp[mt][nt][3] += fmaxf(acck[mt][nt][3] + p1, 0.f);
            }
        __syncthreads();

        // skip2 on h2
        float acco[2][2][4];
        #pragma unroll
        for (int mt = 0; mt < 2; mt++)
            #pragma unroll
            for (int nt = 0; nt < 2; nt++)
                #pragma unroll
                for (int e = 0; e < 4; e++) acco[mt][nt][e] = 0.f;
        #pragma unroll
        for (int ks = 0; ks < 8; ks++) {
            int k0 = ks*8;
            unsigned ah[2][4];
            #pragma unroll
            for (int mt = 0; mt < 2; mt++) {
                int r0 = mt*16 + g;
                ah[mt][0] = tf32cvt(hs[(r0  )*STR + k0 + tg]);
                ah[mt][1] = tf32cvt(hs[(r0+8)*STR + k0 + tg]);
                ah[mt][2] = tf32cvt(hs[(r0  )*STR + k0 + tg + 4]);
                ah[mt][3] = tf32cvt(hs[(r0+8)*STR + k0 + tg + 4]);
            }
            #pragma unroll
            for (int nt = 0; nt < 2; nt++) {
                int fi = (((w*2 + nt)*8 + ks)*32 + lane)*2;
                uint2 bo = *(const uint2*)((const unsigned*)soF + fi);
                #pragma unroll
                for (int mt = 0; mt < 2; mt++)
                    mma_tf32(acco[mt][nt], ah[mt], bo.x, bo.y);
            }
        }
        #pragma unroll
        for (int mt = 0; mt < 2; mt++)
            #pragma unroll
            for (int nt = 0; nt < 2; nt++) {
                int col = w*16 + nt*8 + 2*tg;
                float p0 = bos[col], p1 = bos[col+1];
                poolo[mt][nt][0] += fmaxf(acco[mt][nt][0] + p0, 0.f);
                poolo[mt][nt][1] += fmaxf(acco[mt][nt][1] + p1, 0.f);
                poolo[mt][nt][2] += fmaxf(acco[mt][nt][2] + p0, 0.f);
                poolo[mt][nt][3] += fmaxf(acco[mt][nt][3] + p1, 0.f);
            }
    }
    // pool merge + atomics (layer 1 and 2 slots)
    __syncthreads();
    if (half == 1) {
        #pragma unroll
        for (int mt = 0; mt < 2; mt++)
            #pragma unroll
            for (int nt = 0; nt < 2; nt++)
                #pragma unroll
                for (int e = 0; e < 4; e++) {
                    wsF[wt*32 + (mt*2+nt)*4 + e] = poolp[mt][nt][e];
                    wsF[wt*32 + 16 + (mt*2+nt)*4 + e] = poolo[mt][nt][e];
                }
    }
    __syncthreads();
    if (half == 0) {
        #pragma unroll
        for (int mt = 0; mt < 2; mt++)
            #pragma unroll
            for (int nt = 0; nt < 2; nt++) {
                int col = w*16 + nt*8 + 2*tg;
                #pragma unroll
                for (int e = 0; e < 4; e++) {
                    int c = mt*16 + g + ((e >= 2) ? 8 : 0);
                    int cc = col + (e & 1);
                    float v = poolp[mt][nt][e] + wsF[wt*32 + (mt*2+nt)*4 + e];
                    atomicAdd(&g_pool[c*POOLD + 1*HD + cc], v);
                    float u = poolo[mt][nt][e] + wsF[wt*32 + 16 + (mt*2+nt)*4 + e];
                    atomicAdd(&g_pool[c*POOLD + 2*HD + cc], u);
                }
            }
    }
}

// ---------------- final MLP ----------------------------------------------------
__global__ void k_mlp(const float* __restrict__ p1w, const float* __restrict__ p1b,
                      const float* __restrict__ p2w, const float* __restrict__ p2b,
                      const float* __restrict__ p3w, const float* __restrict__ p3b,
                      float* __restrict__ out) {
    int c = blockIdx.x;
    int t = threadIdx.x;  // 128
    __shared__ float pr[POOLD], y1[128], y2[64];
    for (int i = t; i < POOLD; i += 128) pr[i] = g_pool[c*POOLD + i];
    __syncthreads();
    float s = p1b[t];
    #pragma unroll 4
    for (int d = 0; d < POOLD; d++) s += pr[d] * p1w[d*128 + t];
    y1[t] = fmaxf(s, 0.f);
    __syncthreads();
    if (t < 64) {
        float s2 = p2b[t];
        #pragma unroll 4
        for (int d = 0; d < 128; d++) s2 += y1[d] * p2w[d*64 + t];
        y2[t] = fmaxf(s2, 0.f);
    }
    __syncthreads();
    if (t == 0) {
        float s3 = p3b[0];
        for (int d = 0; d < 64; d++) s3 += y2[d] * p3w[d];
        out[c] = s3;
    }
}

// ---------------- launch -------------------------------------------------------
extern "C" void kernel_launch(void* const* d_in, const int* in_sizes, int n_in,
                              void* d_out, int out_size) {
    const float* nf     = (const float*)d_in[0];
    const void*  opc    = d_in[1];
    const void*  ei     = d_in[2];
    const float* cf     = (const float*)d_in[3];
    const float* op_emb = (const float*)d_in[4];
    const float* ws0    = (const float*)d_in[5];
    const float* wn0    = (const float*)d_in[6];
    const float* b0     = (const float*)d_in[7];
    const float* ws     = (const float*)d_in[8];
    const float* wnn    = (const float*)d_in[9];
    const float* bb     = (const float*)d_in[10];
    const float* skw    = (const float*)d_in[11];
    const float* skb    = (const float*)d_in[12];
    const float* p1w    = (const float*)d_in[13];
    const float* p1b    = (const float*)d_in[14];
    const float* p2w    = (const float*)d_in[15];
    const float* p2b    = (const float*)d_in[16];
    const float* p3w    = (const float*)d_in[17];
    const float* p3b    = (const float*)d_in[18];
    float* out = (float*)d_out;

    const int SMEM_LF = 25216 * (int)sizeof(float);  // 100864 B
    const int SMEM_LL = 25280 * (int)sizeof(float);  // 101120 B
    const int SMEM_PN = 28416 * (int)sizeof(float);  // 113664 B
    cudaFuncSetAttribute(k_layer_first,
                         cudaFuncAttributeMaxDynamicSharedMemorySize, SMEM_LF);
    cudaFuncSetAttribute(k_layer_last,
                         cudaFuncAttributeMaxDynamicSharedMemorySize, SMEM_LL);
    cudaFuncSetAttribute(k_pernode2,
                         cudaFuncAttributeMaxDynamicSharedMemorySize, SMEM_PN);

    float* ph1 = nullptr;
    cudaGetSymbolAddress((void**)&ph1, g_h1);

    k_pre<<<32, 256>>>(opc, ei);
    k_xn_deg<<<(NN*XND + 255)/256, 256>>>(nf, opc, op_emb, ei);
    k_scan_cfg<<<3, 1024>>>(cf, ws0, wn0);
    k_fill<<<(NE + 255)/256, 256>>>(ei);
    k_pernode2<<<157, 256, SMEM_PN>>>(ws0, wn0, b0);
    k_layer_first<<<296, 256, SMEM_LF>>>(ph1, ws, wnn, bb, skw, skb);
    k_layer_last<<<296, 256, SMEM_LL>>>(ph1, ws + HD*HD, wnn + HD*HD, bb + HD,
                                        skw + HD*HD, skb + HD,
                                        skw + 2*HD*HD, skb + 2*HD);
    k_mlp<<<32, 128>>>(p1w, p1b, p2w, p2b, p3w, p3b, out);
}